// round 8
// baseline (speedup 1.0000x reference)
#include <cuda_runtime.h>
#include <cuda_bf16.h>
#include <cstdint>
#include <math.h>

// Problem dims
constexpr int B_ = 4, T_ = 2048, DM_ = 1024, H_ = 16, D_ = 64;
constexpr int NROWS = B_ * T_;           // 8192
constexpr int KP = 3072;                 // int8 3-block: [X1|X1|X0] . [W1|W0|W1]
constexpr int STATE_ELEMS = B_ * H_ * D_ * D_;

// ---------------- scratch (device globals; allocation-free) ----------------
__device__ float g_QKV[(size_t)NROWS * 3072];   // fused Q|K|V fp32
__device__ float g_Y[(size_t)NROWS * DM_];
__device__ float g_alpha[NROWS * H_];
__device__ float g_beta[NROWS * H_];
__device__ float g_Sdump[STATE_ELEMS];
__device__ float g_Wab32[32 * DM_];
__device__ int8_t g_A8[(size_t)NROWS * KP];
__device__ int8_t g_Y8[(size_t)NROWS * KP];
__device__ int8_t g_B8[(size_t)3072 * KP];      // rows: Wq|Wk|Wv output cols
__device__ int8_t g_B8o[(size_t)1024 * KP];
__device__ float g_sx[NROWS];
__device__ float g_sy[NROWS];
__device__ float g_sw[3072];
__device__ float g_swo[1024];

// ---------------------------------------------------------------------------
// INT8 IMMA GEMM: C[M,N] = sA[r]*sB[c]*(16384*P11 + 128*(P10+P01))
// A8[M][3072] = [X1|X1|X0], B8[N][3072] = [W1|W0|W1], per-row scales.
// CTA 128x128, 8 warps (2M x 4N), warp tile 64x32, Kc=64 bytes, 3-stage
// cp.async. Chunks 0-15 -> accA (hi*hi), 16-47 -> accB (cross terms).
// smem rows padded to 80B (R3-proven conflict-free pattern at 16B grain).
// Pipeline: wait_group -> barrier -> load -> compute (R7-proven order).
// ---------------------------------------------------------------------------
__global__ __launch_bounds__(256, 1) void gemm_imma(const int8_t* __restrict__ A,
                                                    const int8_t* __restrict__ Bw,
                                                    const float* __restrict__ sA,
                                                    const float* __restrict__ sB,
                                                    float* __restrict__ C, int ldc) {
    extern __shared__ char sm[];
    const int tid = threadIdx.x;
    const int lane = tid & 31, wid = tid >> 5;
    const int wm = wid & 1, wn = wid >> 1;   // 2 x 4 warp grid
    const int row0 = blockIdx.y * 128;
    const int col0 = blockIdx.x * 128;

    uint32_t sb;
    asm("{ .reg .u64 t; cvta.to.shared.u64 t, %1; cvt.u32.u64 %0, t; }" : "=r"(sb) : "l"(sm));

    // stage = A(128*80 = 10240) + B(10240) = 20480 bytes; 3 stages.
    constexpr uint32_t STG = 20480u;

    int accA[4][4][4];
    int accB[4][4][4];
#pragma unroll
    for (int i = 0; i < 4; ++i)
#pragma unroll
        for (int j = 0; j < 4; ++j)
#pragma unroll
            for (int q = 0; q < 4; ++q) { accA[i][j][q] = 0; accB[i][j][q] = 0; }

    auto load_chunk = [&](int c, int stg) {
        const int8_t* gA = A + (size_t)row0 * KP + c * 64;
        uint32_t ab = sb + (uint32_t)stg * STG;
#pragma unroll
        for (int l = 0; l < 2; ++l) {
            int idx = tid + (l << 8);
            int r = idx >> 2, s = idx & 3;
            uint32_t so = ab + (uint32_t)(r * 80 + s * 16);
            const void* gp = gA + (size_t)r * KP + s * 16;
            asm volatile("cp.async.cg.shared.global [%0], [%1], 16;" :: "r"(so), "l"(gp));
        }
        const int8_t* gB = Bw + (size_t)col0 * KP + c * 64;
        uint32_t bbx = sb + (uint32_t)stg * STG + 10240u;
#pragma unroll
        for (int l = 0; l < 2; ++l) {
            int idx = tid + (l << 8);
            int n = idx >> 2, s = idx & 3;
            uint32_t so = bbx + (uint32_t)(n * 80 + s * 16);
            const void* gp = gB + (size_t)n * KP + s * 16;
            asm volatile("cp.async.cg.shared.global [%0], [%1], 16;" :: "r"(so), "l"(gp));
        }
        asm volatile("cp.async.commit_group;" ::: "memory");
    };

    // per-lane ldmatrix base offsets (BYTES); byte-identical to R3-verified
    // bf16 pattern (16B k-halves), row stride 80B.
    const uint32_t a_base = (uint32_t)((wm * 64 + (lane & 15)) * 80 + ((lane >> 4) << 4));
    const uint32_t b_base = (uint32_t)((wn * 32 + (((lane >> 4) & 1) << 3) + (lane & 7)) * 80 +
                                       (((lane >> 3) & 1) << 4));

    // full-chunk compute into the given accumulator bank
    auto do_chunk = [&](int (&acc)[4][4][4], uint32_t ab) {
        const uint32_t bbs = ab + 10240u;
#pragma unroll
        for (int ks = 0; ks < 2; ++ks) {
            uint32_t af[4][4];
#pragma unroll
            for (int mi = 0; mi < 4; ++mi) {
                uint32_t addr = ab + a_base + (uint32_t)(mi * 16 * 80 + ks * 32);
                asm volatile("ldmatrix.sync.aligned.m8n8.x4.shared.b16 {%0,%1,%2,%3}, [%4];"
                             : "=r"(af[mi][0]), "=r"(af[mi][1]), "=r"(af[mi][2]), "=r"(af[mi][3])
                             : "r"(addr));
            }
            uint32_t bf[4][2];
#pragma unroll
            for (int nb = 0; nb < 2; ++nb) {
                uint32_t addr = bbs + b_base + (uint32_t)(nb * 16 * 80 + ks * 32);
                asm volatile("ldmatrix.sync.aligned.m8n8.x4.shared.b16 {%0,%1,%2,%3}, [%4];"
                             : "=r"(bf[2 * nb][0]), "=r"(bf[2 * nb][1]),
                               "=r"(bf[2 * nb + 1][0]), "=r"(bf[2 * nb + 1][1])
                             : "r"(addr));
            }
#pragma unroll
            for (int mi = 0; mi < 4; ++mi)
#pragma unroll
                for (int ni = 0; ni < 4; ++ni) {
                    asm volatile(
                        "mma.sync.aligned.m16n8k32.row.col.s32.s8.s8.s32 "
                        "{%0,%1,%2,%3}, {%4,%5,%6,%7}, {%8,%9}, {%0,%1,%2,%3};"
                        : "+r"(acc[mi][ni][0]), "+r"(acc[mi][ni][1]),
                          "+r"(acc[mi][ni][2]), "+r"(acc[mi][ni][3])
                        : "r"(af[mi][0]), "r"(af[mi][1]), "r"(af[mi][2]), "r"(af[mi][3]),
                          "r"(bf[ni][0]), "r"(bf[ni][1]));
                }
        }
    };

    load_chunk(0, 0);
    load_chunk(1, 1);

    constexpr int NCH = KP / 64;  // 48
    for (int c = 0; c < NCH; ++c) {
        asm volatile("cp.async.wait_group 1;" ::: "memory");  // this thread's chunk c landed
        __syncthreads();   // all threads' chunk c visible; readers of stage (c-1)%3 done
        if (c + 2 < NCH)
            load_chunk(c + 2, (c + 2) % 3);
        else
            asm volatile("cp.async.commit_group;" ::: "memory");

        const uint32_t ab = sb + (uint32_t)(c % 3) * STG;
        if (c < 16) do_chunk(accA, ab);   // block0: X1*W1
        else        do_chunk(accB, ab);   // blocks1,2: X1*W0 + X0*W1
    }

    // epilogue: C = sx*sw*(16384*accA + 128*accB)
    const int rb = row0 + wm * 64 + (lane >> 2);
    const int cb = col0 + wn * 32 + (lane & 3) * 2;
#pragma unroll
    for (int mi = 0; mi < 4; ++mi) {
        float sx0 = sA[rb + mi * 16];
        float sx1 = sA[rb + mi * 16 + 8];
#pragma unroll
        for (int ni = 0; ni < 4; ++ni) {
            int c0 = cb + ni * 8;
            float sw0 = sB[c0], sw1 = sB[c0 + 1];
            float v0 = 16384.f * (float)accA[mi][ni][0] + 128.f * (float)accB[mi][ni][0];
            float v1 = 16384.f * (float)accA[mi][ni][1] + 128.f * (float)accB[mi][ni][1];
            float v2 = 16384.f * (float)accA[mi][ni][2] + 128.f * (float)accB[mi][ni][2];
            float v3 = 16384.f * (float)accA[mi][ni][3] + 128.f * (float)accB[mi][ni][3];
            int r = rb + mi * 16;
            *(float2*)(C + (size_t)r * ldc + c0) = make_float2(sx0 * sw0 * v0, sx0 * sw1 * v1);
            *(float2*)(C + (size_t)(r + 8) * ldc + c0) =
                make_float2(sx1 * sw0 * v2, sx1 * sw1 * v3);
        }
    }
}

// ---------------------------------------------------------------------------
// Per-row 15-bit quantization: v ~= s*(128*h + l), s = rowmax/16256.
// out[m] = [h(1024) | h(1024) | l(1024)]
// ---------------------------------------------------------------------------
__global__ __launch_bounds__(256) void quant_rows(const float* __restrict__ in,
                                                  int8_t* __restrict__ out,
                                                  float* __restrict__ srow) {
    __shared__ float red[8];
    __shared__ float s_m;
    const int m = blockIdx.x, tid = threadIdx.x;
    float4 v = ((const float4*)(in + (size_t)m * 1024))[tid];
    float mx = fmaxf(fmaxf(fabsf(v.x), fabsf(v.y)), fmaxf(fabsf(v.z), fabsf(v.w)));
#pragma unroll
    for (int o = 16; o; o >>= 1) mx = fmaxf(mx, __shfl_xor_sync(~0u, mx, o));
    if ((tid & 31) == 0) red[tid >> 5] = mx;
    __syncthreads();
    if (tid == 0) {
        float m2 = red[0];
#pragma unroll
        for (int i = 1; i < 8; ++i) m2 = fmaxf(m2, red[i]);
        m2 = fmaxf(m2, 1e-30f);
        s_m = m2;
        srow[m] = m2 * (1.f / 16256.f);
    }
    __syncthreads();
    const float inv = 16256.f / s_m;
    float u[4] = {v.x * inv, v.y * inv, v.z * inv, v.w * inv};
    signed char hq[4], lq[4];
#pragma unroll
    for (int q = 0; q < 4; ++q) {
        float h = rintf(u[q] * 0.0078125f);
        h = fminf(fmaxf(h, -127.f), 127.f);
        float l = rintf(u[q] - 128.f * h);
        l = fminf(fmaxf(l, -127.f), 127.f);
        hq[q] = (signed char)(int)h;
        lq[q] = (signed char)(int)l;
    }
    char4 hc = make_char4(hq[0], hq[1], hq[2], hq[3]);
    char4 lc = make_char4(lq[0], lq[1], lq[2], lq[3]);
    int8_t* o = out + (size_t)m * KP + tid * 4;
    *(char4*)o = hc;
    *(char4*)(o + 1024) = hc;
    *(char4*)(o + 2048) = lc;
}

// Column-max of W[1024][1024] -> per-output-col scale
__global__ __launch_bounds__(256) void colmax_k(const float* __restrict__ W,
                                                float* __restrict__ sw) {
    const int n = blockIdx.x * 256 + threadIdx.x;
    float m = 0.f;
    for (int k = 0; k < 1024; ++k) m = fmaxf(m, fabsf(W[(size_t)k * 1024 + n]));
    sw[n] = fmaxf(m, 1e-30f) * (1.f / 16256.f);
}

// Transpose + quantize W[1024][1024] -> B8[n][3072] = [h | l | h]
__global__ __launch_bounds__(256) void tquant(const float* __restrict__ W,
                                              const float* __restrict__ sw,
                                              int8_t* __restrict__ out) {
    __shared__ float s[32][33];
    const int tx = threadIdx.x & 31, ty = threadIdx.x >> 5;
    const int k0 = blockIdx.y << 5, n0 = blockIdx.x << 5;
#pragma unroll
    for (int r = 0; r < 32; r += 8)
        s[ty + r][tx] = W[(size_t)(k0 + ty + r) * 1024 + n0 + tx];
    __syncthreads();
#pragma unroll
    for (int r = 0; r < 32; r += 8) {
        const int n = n0 + ty + r, k = k0 + tx;
        float u = s[tx][ty + r] / sw[n];
        float h = rintf(u * 0.0078125f);
        h = fminf(fmaxf(h, -127.f), 127.f);
        float l = rintf(u - 128.f * h);
        l = fminf(fmaxf(l, -127.f), 127.f);
        size_t base = (size_t)n * KP + k;
        out[base] = (int8_t)(int)h;
        out[base + 1024] = (int8_t)(int)l;
        out[base + 2048] = (int8_t)(int)h;
    }
}

// Wa/Wb [1024][16] -> Wt32[32][1024] fp32
__global__ __launch_bounds__(256) void gates_prep32(const float* __restrict__ Wa,
                                                    const float* __restrict__ Wb,
                                                    float* __restrict__ out) {
    const int o = blockIdx.x;
    const float* W = (o < 16) ? Wa : Wb;
    const int h = o & 15;
    for (int k = threadIdx.x; k < 1024; k += 256)
        out[(size_t)o * 1024 + k] = W[k * 16 + h];
}

// ---------------------------------------------------------------------------
// Gates: logits = x @ Wt32^T, + bias, sigmoid. Block = 64 rows x 32 outputs.
// ---------------------------------------------------------------------------
__global__ __launch_bounds__(256) void gates64(const float* __restrict__ x,
                                               const float* __restrict__ Wt,
                                               const float* __restrict__ ba,
                                               const float* __restrict__ bb,
                                               float* __restrict__ alpha,
                                               float* __restrict__ beta) {
    __shared__ float xs[64][64];
    __shared__ float ws[32][65];
    const int tid = threadIdx.x;
    const int row0 = blockIdx.x * 64;
    const int rg = tid >> 5;
    const int o = tid & 31;

    float acc[8];
#pragma unroll
    for (int p = 0; p < 8; ++p) acc[p] = 0.f;

    for (int kc = 0; kc < 16; ++kc) {
        __syncthreads();
#pragma unroll
        for (int l = 0; l < 4; ++l) {
            int idx = tid + (l << 8);
            int r = idx >> 4, q = idx & 15;
            float4 v = *(const float4*)(x + (size_t)(row0 + r) * 1024 + kc * 64 + q * 4);
            *(float4*)(&xs[r][q * 4]) = v;
        }
#pragma unroll
        for (int l = 0; l < 2; ++l) {
            int idx = tid + (l << 8);
            int r = idx >> 4, q = idx & 15;
            float4 v = *(const float4*)(Wt + (size_t)r * 1024 + kc * 64 + q * 4);
            ws[r][q * 4 + 0] = v.x; ws[r][q * 4 + 1] = v.y;
            ws[r][q * 4 + 2] = v.z; ws[r][q * 4 + 3] = v.w;
        }
        __syncthreads();
#pragma unroll 8
        for (int k = 0; k < 64; ++k) {
            float wv = ws[o][k];
#pragma unroll
            for (int p = 0; p < 8; ++p)
                acc[p] = fmaf(xs[rg * 8 + p][k], wv, acc[p]);
        }
    }

    const float bias = (o < 16) ? ba[o] : bb[o - 16];
#pragma unroll
    for (int p = 0; p < 8; ++p) {
        float r = 1.f / (1.f + expf(-(acc[p] + bias)));
        int row = row0 + rg * 8 + p;
        if (o < 16) alpha[(size_t)row * 16 + o] = r;
        else        beta[(size_t)row * 16 + (o - 16)] = r;
    }
}

// ---------------------------------------------------------------------------
// K normalize over fused QKV buffer (K = cols [1024,2048))
// ---------------------------------------------------------------------------
__global__ __launch_bounds__(256) void knorm2(float* __restrict__ QKV) {
    const int w = (int)((blockIdx.x * blockDim.x + threadIdx.x) >> 5);
    const int lane = threadIdx.x & 31;
    if (w >= NROWS * H_) return;
    const int n = w >> 4, h = w & 15;
    float2* p = (float2*)(QKV + (size_t)n * 3072 + 1024 + h * 64);
    float2 v = p[lane];
    float ss = v.x * v.x + v.y * v.y;
#pragma unroll
    for (int m = 16; m; m >>= 1) ss += __shfl_xor_sync(~0u, ss, m);
    float inv = 1.f / fmaxf(sqrtf(ss), 1e-12f);
    v.x *= inv; v.y *= inv;
    p[lane] = v;
}

// ---------------------------------------------------------------------------
// Sequential scan: 128 blocks (one per (b,h,row-half)), 128 threads.
// ---------------------------------------------------------------------------
__global__ __launch_bounds__(128) void scan_kernel2(
    const float* __restrict__ QKV, const float* __restrict__ alpha,
    const float* __restrict__ beta, const float* __restrict__ S0,
    float* __restrict__ Y, float* __restrict__ Sout) {
    constexpr int CH = 16;
    __shared__ float cq[2][CH][64];
    __shared__ float ck[2][CH][64];
    __shared__ float cv[2][CH][32];
    __shared__ float ca[2][CH];
    __shared__ float cb[2][CH];

    const int tid = threadIdx.x;
    const int bh2 = blockIdx.x;
    const int bh = bh2 >> 1, half = bh2 & 1;
    const int b = bh >> 4, h = bh & 15;
    const int i = tid >> 2;
    const int gi = half * 32 + i;
    const int jg = tid & 3;
    const int j0 = jg << 4;

    float4 s4[4];
    {
        const float4* sp = (const float4*)(S0 + ((size_t)bh * 64 + gi) * 64 + j0);
        s4[0] = sp[0]; s4[1] = sp[1]; s4[2] = sp[2]; s4[3] = sp[3];
    }

    const float* rowQ = QKV + (size_t)b * T_ * 3072 + (size_t)h * 64;

    auto load_chunk = [&](int t0, int buf) {
#pragma unroll
        for (int l = 0; l < 2; ++l) {
            int idx = tid + (l << 7);
            int st = idx >> 4, f = (idx & 15) << 2;
            const float* base = rowQ + (size_t)(t0 + st) * 3072;
            *(float4*)(&cq[buf][st][f]) = *(const float4*)(base + f);
            *(float4*)(&ck[buf][st][f]) = *(const float4*)(base + 1024 + f);
        }
        {
            int st = tid >> 3, f = (tid & 7) << 2;
            const float* base = rowQ + (size_t)(t0 + st) * 3072 + 2048 + half * 32;
            *(float4*)(&cv[buf][st][f]) = *(const float4*)(base + f);
        }
        if (tid < CH)
            ca[buf][tid] = alpha[((size_t)b * T_ + t0 + tid) * H_ + h];
        else if (tid < 2 * CH)
            cb[buf][tid - CH] = beta[((size_t)b * T_ + t0 + tid - CH) * H_ + h];
    };

    const size_t ybase = (size_t)b * T_ * DM_ + (size_t)h * 64 + gi;
    const int nch = T_ / CH;
    load_chunk(0, 0);
    __syncthreads();

    for (int c = 0; c < nch; ++c) {
        const int buf = c & 1;
        if (c + 1 < nch) load_chunk((c + 1) * CH, buf ^ 1);

#pragma unroll 4
        for (int s = 0; s < CH; ++s) {
            const float a = ca[buf][s];
            const float bg = cb[buf][s];
            const float bv = bg * cv[buf][s][i];
            const float4* kp = (const float4*)(&ck[buf][s][j0]);
            const float4* qp = (const float4*)(&cq[buf][s][j0]);
            float partial = 0.f;
#pragma unroll
            for (int v = 0; v < 4; ++v) {
                float4 kk = kp[v];
                float4 qq = qp[v];
                s4[v].x = fmaf(a, s4[v].x, bv * kk.x); partial = fmaf(s4[v].x, qq.x, partial);
                s4[v].y = fmaf(a, s4[v].y, bv * kk.y); partial = fmaf(s4[v].y, qq.y, partial);
                s4[v].z = fmaf(a, s4[v].z, bv * kk.z); partial = fmaf(s4[v].z, qq.z, partial);
                s4[v].w = fmaf(a, s4[v].w, bv * kk.w); partial = fmaf(s4[v].w, qq.w, partial);
            }
            partial += __shfl_xor_sync(~0u, partial, 1);
            partial += __shfl_xor_sync(~0u, partial, 2);
            if (jg == 0)
                Y[ybase + (size_t)(c * CH + s) * DM_] = partial;
        }
        __syncthreads();
    }

    float4* so = (float4*)(Sout + ((size_t)bh * 64 + gi) * 64 + j0);
    so[0] = s4[0]; so[1] = s4[1]; so[2] = s4[2]; so[3] = s4[3];
}

// ---------------------------------------------------------------------------
extern "C" void kernel_launch(void* const* d_in, const int* in_sizes, int n_in,
                              void* d_out, int out_size) {
    (void)in_sizes; (void)n_in;
    const float* x  = (const float*)d_in[0];
    const float* S0 = (const float*)d_in[1];
    const float* Wq = (const float*)d_in[2];
    const float* Wk = (const float*)d_in[3];
    const float* Wv = (const float*)d_in[4];
    const float* Wa = (const float*)d_in[5];
    const float* ba = (const float*)d_in[6];
    const float* Wb = (const float*)d_in[7];
    const float* bb = (const float*)d_in[8];
    const float* Wo = (const float*)d_in[9];
    float* out = (float*)d_out;

    float *QKVd, *Yd, *al, *be, *Sdump, *Wab32, *sx, *sy, *sw, *swo;
    int8_t *A8, *Y8, *B8, *B8o;
    cudaGetSymbolAddress((void**)&QKVd, g_QKV);
    cudaGetSymbolAddress((void**)&Yd, g_Y);
    cudaGetSymbolAddress((void**)&al, g_alpha);
    cudaGetSymbolAddress((void**)&be, g_beta);
    cudaGetSymbolAddress((void**)&Sdump, g_Sdump);
    cudaGetSymbolAddress((void**)&Wab32, g_Wab32);
    cudaGetSymbolAddress((void**)&A8, g_A8);
    cudaGetSymbolAddress((void**)&Y8, g_Y8);
    cudaGetSymbolAddress((void**)&B8, g_B8);
    cudaGetSymbolAddress((void**)&B8o, g_B8o);
    cudaGetSymbolAddress((void**)&sx, g_sx);
    cudaGetSymbolAddress((void**)&sy, g_sy);
    cudaGetSymbolAddress((void**)&sw, g_sw);
    cudaGetSymbolAddress((void**)&swo, g_swo);

    float* Sout = (out_size >= NROWS * DM_ + STATE_ELEMS) ? out + (size_t)NROWS * DM_ : Sdump;

    constexpr int GSMEM = 3 * 20480;   // 61440 per CTA (3-stage)
    cudaFuncSetAttribute(gemm_imma, cudaFuncAttributeMaxDynamicSharedMemorySize, GSMEM);

    // quantize activations + weights
    quant_rows<<<NROWS, 256>>>(x, A8, sx);
    colmax_k<<<4, 256>>>(Wq, sw);
    colmax_k<<<4, 256>>>(Wk, sw + 1024);
    colmax_k<<<4, 256>>>(Wv, sw + 2048);
    colmax_k<<<4, 256>>>(Wo, swo);
    tquant<<<dim3(32, 32), 256>>>(Wq, sw, B8);
    tquant<<<dim3(32, 32), 256>>>(Wk, sw + 1024, B8 + (size_t)1024 * KP);
    tquant<<<dim3(32, 32), 256>>>(Wv, sw + 2048, B8 + (size_t)2048 * KP);
    tquant<<<dim3(32, 32), 256>>>(Wo, swo, B8o);
    gates_prep32<<<32, 256>>>(Wa, Wb, Wab32);

    // fused QKV projection (int8 tensor pipe)
    gemm_imma<<<dim3(3072 / 128, NROWS / 128), 256, GSMEM>>>(A8, B8, sx, sw, QKVd, 3072);
    gates64<<<NROWS / 64, 256>>>(x, Wab32, ba, bb, al, be);

    // normalize K, run the recurrence
    knorm2<<<(NROWS * H_ * 32) / 256, 256>>>(QKVd);
    scan_kernel2<<<128, 128>>>(QKVd, al, be, S0, Yd, Sout);

    // output projection
    quant_rows<<<NROWS, 256>>>(Yd, Y8, sy);
    gemm_imma<<<dim3(1024 / 128, NROWS / 128), 256, GSMEM>>>(Y8, B8o, sy, swo, out, 1024);
}

// round 9
// speedup vs baseline: 2.2932x; 2.2932x over previous
#include <cuda_runtime.h>
#include <cuda_fp16.h>
#include <cstdint>
#include <math.h>

// Problem dims
constexpr int B_ = 4, T_ = 2048, DM_ = 1024, H_ = 16, D_ = 64;
constexpr int NROWS = B_ * T_;           // 8192
constexpr int KP = 2048;                 // fp16 2-term split: [ah|al] . [bh|bh]
constexpr int STATE_ELEMS = B_ * H_ * D_ * D_;

// ---------------- scratch (device globals; allocation-free) ----------------
__device__ float g_QKV[(size_t)NROWS * 3072];   // fused Q|K|V fp32
__device__ float g_Y[(size_t)NROWS * DM_];
__device__ float g_alpha[NROWS * H_];
__device__ float g_beta[NROWS * H_];
__device__ float g_Sdump[STATE_ELEMS];
__device__ float g_Wab32[32 * DM_];
__device__ __half g_A2[(size_t)NROWS * KP];
__device__ __half g_Y2[(size_t)NROWS * KP];
__device__ __half g_Wqkv[(size_t)3072 * KP];   // rows: Wq|Wk|Wv output cols
__device__ __half g_Wto[(size_t)DM_ * KP];

// ---------------------------------------------------------------------------
// fp16 mma.sync GEMM: C[8192, N] = A'[8192,2048] @ B'[N,2048]^T
// CTA 128x128, 4 warps (2M x 2N), warp tile 64x64, Kc=64, 3-stage cp.async,
// 2 CTAs/SM. smem rows padded to 72 halves (144B), conflict-free (R4).
// Pipeline order: wait_group -> barrier -> load -> compute (R7-proven).
// ---------------------------------------------------------------------------
__global__ __launch_bounds__(128, 2) void gemm_mma(const __half* __restrict__ A,
                                                   const __half* __restrict__ Bw,
                                                   float* __restrict__ C, int ldc) {
    extern __shared__ char sm[];
    const int tid = threadIdx.x;
    const int lane = tid & 31, wid = tid >> 5;
    const int wm = wid & 1, wn = (wid >> 1) & 1;   // 2 x 2 warp grid
    const int row0 = blockIdx.y * 128;
    const int col0 = blockIdx.x * 128;

    uint32_t sb;
    asm("{ .reg .u64 t; cvta.to.shared.u64 t, %1; cvt.u32.u64 %0, t; }" : "=r"(sb) : "l"(sm));

    // stage = A(128*144 = 18432) + B(18432) = 36864 bytes; 3 stages.
    constexpr uint32_t STG = 36864u;

    float acc[4][8][4];
#pragma unroll
    for (int i = 0; i < 4; ++i)
#pragma unroll
        for (int j = 0; j < 8; ++j)
#pragma unroll
            for (int q = 0; q < 4; ++q) acc[i][j][q] = 0.f;

    auto load_chunk = [&](int c, int stg) {
        const __half* gA = A + (size_t)row0 * KP + c * 64;
        uint32_t ab = sb + (uint32_t)stg * STG;
#pragma unroll
        for (int l = 0; l < 8; ++l) {
            int idx = tid + (l << 7);
            int r = idx >> 3, s = idx & 7;
            uint32_t so = ab + (uint32_t)(r * 144 + s * 16);
            const void* gp = gA + (size_t)r * KP + s * 8;
            asm volatile("cp.async.cg.shared.global [%0], [%1], 16;" :: "r"(so), "l"(gp));
        }
        const __half* gB = Bw + (size_t)col0 * KP + c * 64;
        uint32_t bbx = sb + (uint32_t)stg * STG + 18432u;
#pragma unroll
        for (int l = 0; l < 8; ++l) {
            int idx = tid + (l << 7);
            int n = idx >> 3, s = idx & 7;
            uint32_t so = bbx + (uint32_t)(n * 144 + s * 16);
            const void* gp = gB + (size_t)n * KP + s * 8;
            asm volatile("cp.async.cg.shared.global [%0], [%1], 16;" :: "r"(so), "l"(gp));
        }
        asm volatile("cp.async.commit_group;" ::: "memory");
    };

    // per-lane ldmatrix base offsets (halves); pad-72 addressing from R4
    const uint32_t a_base = (uint32_t)((wm * 64 + (lane & 15)) * 72 + ((lane >> 4) << 3));
    const uint32_t b_base = (uint32_t)((wn * 64 + (((lane >> 4) & 1) << 3) + (lane & 7)) * 72 +
                                       (((lane >> 3) & 1) << 3));

    load_chunk(0, 0);
    load_chunk(1, 1);

    constexpr int NCH = KP / 64;  // 32
    for (int c = 0; c < NCH; ++c) {
        asm volatile("cp.async.wait_group 1;" ::: "memory");  // this thread's chunk c landed
        __syncthreads();   // all threads' chunk c visible; readers of stage (c-1)%3 done
        if (c + 2 < NCH)
            load_chunk(c + 2, (c + 2) % 3);
        else
            asm volatile("cp.async.commit_group;" ::: "memory");  // keep group count in step

        const uint32_t ab = sb + (uint32_t)(c % 3) * STG;
        const uint32_t bbs = ab + 18432u;
#pragma unroll
        for (int ks = 0; ks < 4; ++ks) {
            uint32_t af[4][4];
#pragma unroll
            for (int mi = 0; mi < 4; ++mi) {
                uint32_t addr = ab + (a_base + (uint32_t)(mi * 16 * 72 + ks * 16)) * 2;
                asm volatile("ldmatrix.sync.aligned.m8n8.x4.shared.b16 {%0,%1,%2,%3}, [%4];"
                             : "=r"(af[mi][0]), "=r"(af[mi][1]), "=r"(af[mi][2]), "=r"(af[mi][3])
                             : "r"(addr));
            }
            uint32_t bf[8][2];
#pragma unroll
            for (int nb = 0; nb < 4; ++nb) {
                uint32_t addr = bbs + (b_base + (uint32_t)(nb * 16 * 72 + ks * 16)) * 2;
                asm volatile("ldmatrix.sync.aligned.m8n8.x4.shared.b16 {%0,%1,%2,%3}, [%4];"
                             : "=r"(bf[2 * nb][0]), "=r"(bf[2 * nb][1]),
                               "=r"(bf[2 * nb + 1][0]), "=r"(bf[2 * nb + 1][1])
                             : "r"(addr));
            }
#pragma unroll
            for (int mi = 0; mi < 4; ++mi)
#pragma unroll
                for (int ni = 0; ni < 8; ++ni) {
                    asm volatile(
                        "mma.sync.aligned.m16n8k16.row.col.f32.f16.f16.f32 "
                        "{%0,%1,%2,%3}, {%4,%5,%6,%7}, {%8,%9}, {%0,%1,%2,%3};"
                        : "+f"(acc[mi][ni][0]), "+f"(acc[mi][ni][1]),
                          "+f"(acc[mi][ni][2]), "+f"(acc[mi][ni][3])
                        : "r"(af[mi][0]), "r"(af[mi][1]), "r"(af[mi][2]), "r"(af[mi][3]),
                          "r"(bf[ni][0]), "r"(bf[ni][1]));
                }
        }
    }

    const int rb = row0 + wm * 64 + (lane >> 2);
    const int cb = col0 + wn * 64 + (lane & 3) * 2;
#pragma unroll
    for (int mi = 0; mi < 4; ++mi)
#pragma unroll
        for (int ni = 0; ni < 8; ++ni) {
            int r = rb + mi * 16, cc = cb + ni * 8;
            *(float2*)(C + (size_t)r * ldc + cc) = make_float2(acc[mi][ni][0], acc[mi][ni][1]);
            *(float2*)(C + (size_t)(r + 8) * ldc + cc) =
                make_float2(acc[mi][ni][2], acc[mi][ni][3]);
        }
}

// ---------------------------------------------------------------------------
// fp32 -> 2-term fp16 split: out[m] = [hi(1024) | lo(1024)]  (exact to 22 bits)
// ---------------------------------------------------------------------------
__global__ __launch_bounds__(256) void convert_split2(const float* __restrict__ in,
                                                      __half* __restrict__ out) {
    size_t i = (size_t)blockIdx.x * 256 + threadIdx.x;   // float4 group id
    float4 v = ((const float4*)in)[i];
    size_t m = i >> 8;
    int k4 = (int)(i & 255) << 2;
    __half h0 = __float2half(v.x), h1 = __float2half(v.y);
    __half h2 = __float2half(v.z), h3 = __float2half(v.w);
    __half l0 = __float2half(v.x - __half2float(h0));
    __half l1 = __float2half(v.y - __half2float(h1));
    __half l2 = __float2half(v.z - __half2float(h2));
    __half l3 = __float2half(v.w - __half2float(h3));
    __half2* oh = (__half2*)(out + m * KP + k4);
    oh[0] = __halves2half2(h0, h1);
    oh[1] = __halves2half2(h2, h3);
    __half2* ol = (__half2*)(out + m * KP + 1024 + k4);
    ol[0] = __halves2half2(l0, l1);
    ol[1] = __halves2half2(l2, l3);
}

// W[1024][1024] fp32 -> B'[n][2048] = [hi | hi]  (transposed, K-major)
__global__ __launch_bounds__(256) void transpose_split2(const float* __restrict__ W,
                                                        __half* __restrict__ out) {
    __shared__ float s[32][33];
    const int tx = threadIdx.x & 31, ty = threadIdx.x >> 5;
    const int k0 = blockIdx.y << 5, n0 = blockIdx.x << 5;
#pragma unroll
    for (int r = 0; r < 32; r += 8)
        s[ty + r][tx] = W[(size_t)(k0 + ty + r) * 1024 + n0 + tx];
    __syncthreads();
#pragma unroll
    for (int r = 0; r < 32; r += 8) {
        const int n = n0 + ty + r, k = k0 + tx;
        __half h = __float2half(s[tx][ty + r]);
        out[(size_t)n * KP + k] = h;
        out[(size_t)n * KP + 1024 + k] = h;
    }
}

// Wa/Wb [1024][16] -> Wt32[32][1024] fp32
__global__ __launch_bounds__(256) void gates_prep32(const float* __restrict__ Wa,
                                                    const float* __restrict__ Wb,
                                                    float* __restrict__ out) {
    const int o = blockIdx.x;
    const float* W = (o < 16) ? Wa : Wb;
    const int h = o & 15;
    for (int k = threadIdx.x; k < 1024; k += 256)
        out[(size_t)o * 1024 + k] = W[k * 16 + h];
}

// ---------------------------------------------------------------------------
// Gates: logits = x @ Wt32^T, + bias, sigmoid. Block = 64 rows x 32 outputs.
// ---------------------------------------------------------------------------
__global__ __launch_bounds__(256) void gates64(const float* __restrict__ x,
                                               const float* __restrict__ Wt,
                                               const float* __restrict__ ba,
                                               const float* __restrict__ bb,
                                               float* __restrict__ alpha,
                                               float* __restrict__ beta) {
    __shared__ float xs[64][64];
    __shared__ float ws[32][65];
    const int tid = threadIdx.x;
    const int row0 = blockIdx.x * 64;
    const int rg = tid >> 5;
    const int o = tid & 31;

    float acc[8];
#pragma unroll
    for (int p = 0; p < 8; ++p) acc[p] = 0.f;

    for (int kc = 0; kc < 16; ++kc) {
        __syncthreads();
#pragma unroll
        for (int l = 0; l < 4; ++l) {
            int idx = tid + (l << 8);
            int r = idx >> 4, q = idx & 15;
            float4 v = *(const float4*)(x + (size_t)(row0 + r) * 1024 + kc * 64 + q * 4);
            *(float4*)(&xs[r][q * 4]) = v;
        }
#pragma unroll
        for (int l = 0; l < 2; ++l) {
            int idx = tid + (l << 8);
            int r = idx >> 4, q = idx & 15;
            float4 v = *(const float4*)(Wt + (size_t)r * 1024 + kc * 64 + q * 4);
            ws[r][q * 4 + 0] = v.x; ws[r][q * 4 + 1] = v.y;
            ws[r][q * 4 + 2] = v.z; ws[r][q * 4 + 3] = v.w;
        }
        __syncthreads();
#pragma unroll 8
        for (int k = 0; k < 64; ++k) {
            float wv = ws[o][k];
#pragma unroll
            for (int p = 0; p < 8; ++p)
                acc[p] = fmaf(xs[rg * 8 + p][k], wv, acc[p]);
        }
    }

    const float bias = (o < 16) ? ba[o] : bb[o - 16];
#pragma unroll
    for (int p = 0; p < 8; ++p) {
        float r = 1.f / (1.f + expf(-(acc[p] + bias)));
        int row = row0 + rg * 8 + p;
        if (o < 16) alpha[(size_t)row * 16 + o] = r;
        else        beta[(size_t)row * 16 + (o - 16)] = r;
    }
}

// ---------------------------------------------------------------------------
// K normalize over fused QKV buffer (K = cols [1024,2048))
// ---------------------------------------------------------------------------
__global__ __launch_bounds__(256) void knorm2(float* __restrict__ QKV) {
    const int w = (int)((blockIdx.x * blockDim.x + threadIdx.x) >> 5);
    const int lane = threadIdx.x & 31;
    if (w >= NROWS * H_) return;
    const int n = w >> 4, h = w & 15;
    float2* p = (float2*)(QKV + (size_t)n * 3072 + 1024 + h * 64);
    float2 v = p[lane];
    float ss = v.x * v.x + v.y * v.y;
#pragma unroll
    for (int m = 16; m; m >>= 1) ss += __shfl_xor_sync(~0u, ss, m);
    float inv = 1.f / fmaxf(sqrtf(ss), 1e-12f);
    v.x *= inv; v.y *= inv;
    p[lane] = v;
}

// ---------------------------------------------------------------------------
// Sequential scan: 128 blocks (one per (b,h,row-half)), 128 threads.
// ---------------------------------------------------------------------------
__global__ __launch_bounds__(128) void scan_kernel2(
    const float* __restrict__ QKV, const float* __restrict__ alpha,
    const float* __restrict__ beta, const float* __restrict__ S0,
    float* __restrict__ Y, float* __restrict__ Sout) {
    constexpr int CH = 16;
    __shared__ float cq[2][CH][64];
    __shared__ float ck[2][CH][64];
    __shared__ float cv[2][CH][32];
    __shared__ float ca[2][CH];
    __shared__ float cb[2][CH];

    const int tid = threadIdx.x;
    const int bh2 = blockIdx.x;
    const int bh = bh2 >> 1, half = bh2 & 1;
    const int b = bh >> 4, h = bh & 15;
    const int i = tid >> 2;
    const int gi = half * 32 + i;
    const int jg = tid & 3;
    const int j0 = jg << 4;

    float4 s4[4];
    {
        const float4* sp = (const float4*)(S0 + ((size_t)bh * 64 + gi) * 64 + j0);
        s4[0] = sp[0]; s4[1] = sp[1]; s4[2] = sp[2]; s4[3] = sp[3];
    }

    const float* rowQ = QKV + (size_t)b * T_ * 3072 + (size_t)h * 64;

    auto load_chunk = [&](int t0, int buf) {
#pragma unroll
        for (int l = 0; l < 2; ++l) {
            int idx = tid + (l << 7);
            int st = idx >> 4, f = (idx & 15) << 2;
            const float* base = rowQ + (size_t)(t0 + st) * 3072;
            *(float4*)(&cq[buf][st][f]) = *(const float4*)(base + f);
            *(float4*)(&ck[buf][st][f]) = *(const float4*)(base + 1024 + f);
        }
        {
            int st = tid >> 3, f = (tid & 7) << 2;
            const float* base = rowQ + (size_t)(t0 + st) * 3072 + 2048 + half * 32;
            *(float4*)(&cv[buf][st][f]) = *(const float4*)(base + f);
        }
        if (tid < CH)
            ca[buf][tid] = alpha[((size_t)b * T_ + t0 + tid) * H_ + h];
        else if (tid < 2 * CH)
            cb[buf][tid - CH] = beta[((size_t)b * T_ + t0 + tid - CH) * H_ + h];
    };

    const size_t ybase = (size_t)b * T_ * DM_ + (size_t)h * 64 + gi;
    const int nch = T_ / CH;
    load_chunk(0, 0);
    __syncthreads();

    for (int c = 0; c < nch; ++c) {
        const int buf = c & 1;
        if (c + 1 < nch) load_chunk((c + 1) * CH, buf ^ 1);

#pragma unroll 4
        for (int s = 0; s < CH; ++s) {
            const float a = ca[buf][s];
            const float bg = cb[buf][s];
            const float bv = bg * cv[buf][s][i];
            const float4* kp = (const float4*)(&ck[buf][s][j0]);
            const float4* qp = (const float4*)(&cq[buf][s][j0]);
            float partial = 0.f;
#pragma unroll
            for (int v = 0; v < 4; ++v) {
                float4 kk = kp[v];
                float4 qq = qp[v];
                s4[v].x = fmaf(a, s4[v].x, bv * kk.x); partial = fmaf(s4[v].x, qq.x, partial);
                s4[v].y = fmaf(a, s4[v].y, bv * kk.y); partial = fmaf(s4[v].y, qq.y, partial);
                s4[v].z = fmaf(a, s4[v].z, bv * kk.z); partial = fmaf(s4[v].z, qq.z, partial);
                s4[v].w = fmaf(a, s4[v].w, bv * kk.w); partial = fmaf(s4[v].w, qq.w, partial);
            }
            partial += __shfl_xor_sync(~0u, partial, 1);
            partial += __shfl_xor_sync(~0u, partial, 2);
            if (jg == 0)
                Y[ybase + (size_t)(c * CH + s) * DM_] = partial;
        }
        __syncthreads();
    }

    float4* so = (float4*)(Sout + ((size_t)bh * 64 + gi) * 64 + j0);
    so[0] = s4[0]; so[1] = s4[1]; so[2] = s4[2]; so[3] = s4[3];
}

// ---------------------------------------------------------------------------
extern "C" void kernel_launch(void* const* d_in, const int* in_sizes, int n_in,
                              void* d_out, int out_size) {
    (void)in_sizes; (void)n_in;
    const float* x  = (const float*)d_in[0];
    const float* S0 = (const float*)d_in[1];
    const float* Wq = (const float*)d_in[2];
    const float* Wk = (const float*)d_in[3];
    const float* Wv = (const float*)d_in[4];
    const float* Wa = (const float*)d_in[5];
    const float* ba = (const float*)d_in[6];
    const float* Wb = (const float*)d_in[7];
    const float* bb = (const float*)d_in[8];
    const float* Wo = (const float*)d_in[9];
    float* out = (float*)d_out;

    float *QKVd, *Yd, *al, *be, *Sdump, *Wab32;
    __half *A2, *Y2, *Wqkv, *Wto;
    cudaGetSymbolAddress((void**)&QKVd, g_QKV);
    cudaGetSymbolAddress((void**)&Yd, g_Y);
    cudaGetSymbolAddress((void**)&al, g_alpha);
    cudaGetSymbolAddress((void**)&be, g_beta);
    cudaGetSymbolAddress((void**)&Sdump, g_Sdump);
    cudaGetSymbolAddress((void**)&Wab32, g_Wab32);
    cudaGetSymbolAddress((void**)&A2, g_A2);
    cudaGetSymbolAddress((void**)&Y2, g_Y2);
    cudaGetSymbolAddress((void**)&Wqkv, g_Wqkv);
    cudaGetSymbolAddress((void**)&Wto, g_Wto);

    float* Sout = (out_size >= NROWS * DM_ + STATE_ELEMS) ? out + (size_t)NROWS * DM_ : Sdump;

    constexpr int GSMEM = 3 * 36864;   // 110592 per CTA (3-stage)
    cudaFuncSetAttribute(gemm_mma, cudaFuncAttributeMaxDynamicSharedMemorySize, GSMEM);

    convert_split2<<<NROWS, 256>>>(x, A2);
    transpose_split2<<<dim3(32, 32), 256>>>(Wq, Wqkv);
    transpose_split2<<<dim3(32, 32), 256>>>(Wk, Wqkv + (size_t)1024 * KP);
    transpose_split2<<<dim3(32, 32), 256>>>(Wv, Wqkv + (size_t)2048 * KP);
    gates_prep32<<<32, 256>>>(Wa, Wb, Wab32);
    gemm_mma<<<dim3(3072 / 128, NROWS / 128), 128, GSMEM>>>(A2, Wqkv, QKVd, 3072);
    gates64<<<NROWS / 64, 256>>>(x, Wab32, ba, bb, al, be);
    knorm2<<<(NROWS * H_ * 32) / 256, 256>>>(QKVd);
    scan_kernel2<<<128, 128>>>(QKVd, al, be, S0, Yd, Sout);
    convert_split2<<<NROWS, 256>>>(Yd, Y2);
    transpose_split2<<<dim3(32, 32), 256>>>(Wo, Wto);
    gemm_mma<<<dim3(1024 / 128, NROWS / 128), 128, GSMEM>>>(Y2, Wto, out, 1024);
}

// round 10
// speedup vs baseline: 2.3234x; 1.0132x over previous
#include <cuda_runtime.h>
#include <cuda_fp16.h>
#include <cstdint>
#include <math.h>

// Problem dims
constexpr int B_ = 4, T_ = 2048, DM_ = 1024, H_ = 16, D_ = 64;
constexpr int NROWS = B_ * T_;           // 8192
constexpr int KP = 2048;                 // fp16 2-term split: [ah|al] . [bh|bh]
constexpr int STATE_ELEMS = B_ * H_ * D_ * D_;

// ---------------- scratch (device globals; allocation-free) ----------------
__device__ float g_QKV[(size_t)NROWS * 3072];   // fused Q|K|V fp32
__device__ float g_Y[(size_t)NROWS * DM_];
__device__ float g_alpha[NROWS * H_];
__device__ float g_beta[NROWS * H_];
__device__ float g_Sdump[STATE_ELEMS];
__device__ float g_Wab32[32 * DM_];
__device__ __half g_A2[(size_t)NROWS * KP];
__device__ __half g_Y2[(size_t)NROWS * KP];
__device__ __half g_Wqkv[(size_t)3072 * KP];   // rows: Wq|Wk|Wv output cols
__device__ __half g_Wto[(size_t)DM_ * KP];

// ---------------------------------------------------------------------------
// fp16 mma.sync GEMM: C[8192, N] = A'[8192,2048] @ B'[N,2048]^T
// R4-proven structure: CTA 128x128, 8 warps (2M x 4N), warp tile 64x32,
// Kc=64, double-buffered cp.async, 2 CTAs/SM (4 warps/SMSP for latency
// hiding). smem rows padded to 72 halves (144B), conflict-free.
// ---------------------------------------------------------------------------
__global__ __launch_bounds__(256, 2) void gemm_mma(const __half* __restrict__ A,
                                                   const __half* __restrict__ Bw,
                                                   float* __restrict__ C, int ldc) {
    extern __shared__ char sm[];
    const int tid = threadIdx.x;
    const int lane = tid & 31, wid = tid >> 5;
    const int wm = wid & 1, wn = wid >> 1;       // 2 x 4 warp grid
    const int row0 = blockIdx.y * 128;
    const int col0 = blockIdx.x * 128;

    uint32_t sb;
    asm("{ .reg .u64 t; cvta.to.shared.u64 t, %1; cvt.u32.u64 %0, t; }" : "=r"(sb) : "l"(sm));

    // per-stage: A 128*72*2 = 18432 B, B same. stage = 36864; two stages.
    const uint32_t A_OFF[2] = {0u, 36864u};
    const uint32_t B_OFF[2] = {18432u, 36864u + 18432u};

    float acc[4][4][4];
#pragma unroll
    for (int i = 0; i < 4; ++i)
#pragma unroll
        for (int j = 0; j < 4; ++j)
#pragma unroll
            for (int q = 0; q < 4; ++q) acc[i][j][q] = 0.f;

    auto load_chunk = [&](int c, int buf) {
        const __half* gA = A + (size_t)row0 * KP + c * 64;
        uint32_t ab = sb + A_OFF[buf];
#pragma unroll
        for (int l = 0; l < 4; ++l) {
            int idx = tid + (l << 8);
            int r = idx >> 3, s = idx & 7;
            uint32_t so = ab + (uint32_t)(r * 144 + s * 16);
            const void* gp = gA + (size_t)r * KP + s * 8;
            asm volatile("cp.async.cg.shared.global [%0], [%1], 16;" :: "r"(so), "l"(gp));
        }
        const __half* gB = Bw + (size_t)col0 * KP + c * 64;
        uint32_t bbx = sb + B_OFF[buf];
#pragma unroll
        for (int l = 0; l < 4; ++l) {
            int idx = tid + (l << 8);
            int n = idx >> 3, s = idx & 7;
            uint32_t so = bbx + (uint32_t)(n * 144 + s * 16);
            const void* gp = gB + (size_t)n * KP + s * 8;
            asm volatile("cp.async.cg.shared.global [%0], [%1], 16;" :: "r"(so), "l"(gp));
        }
        asm volatile("cp.async.commit_group;" ::: "memory");
    };

    // per-lane ldmatrix base offsets (halves); pad-72 addressing from R4
    const uint32_t a_base = (uint32_t)((wm * 64 + (lane & 15)) * 72 + ((lane >> 4) << 3));
    const uint32_t b_base = (uint32_t)((wn * 32 + (((lane >> 4) & 1) << 3) + (lane & 7)) * 72 +
                                       (((lane >> 3) & 1) << 3));

    load_chunk(0, 0);

    constexpr int NCH = KP / 64;  // 32
    for (int c = 0; c < NCH; ++c) {
        const int buf = c & 1;
        if (c + 1 < NCH) {
            load_chunk(c + 1, buf ^ 1);
            asm volatile("cp.async.wait_group 1;" ::: "memory");
        } else {
            asm volatile("cp.async.wait_group 0;" ::: "memory");
        }
        __syncthreads();

        const uint32_t ab = sb + A_OFF[buf];
        const uint32_t bbs = sb + B_OFF[buf];
#pragma unroll
        for (int ks = 0; ks < 4; ++ks) {
            uint32_t af[4][4];
#pragma unroll
            for (int mi = 0; mi < 4; ++mi) {
                uint32_t addr = ab + (a_base + (uint32_t)(mi * 16 * 72 + ks * 16)) * 2;
                asm volatile("ldmatrix.sync.aligned.m8n8.x4.shared.b16 {%0,%1,%2,%3}, [%4];"
                             : "=r"(af[mi][0]), "=r"(af[mi][1]), "=r"(af[mi][2]), "=r"(af[mi][3])
                             : "r"(addr));
            }
            uint32_t bf[4][2];
#pragma unroll
            for (int nb = 0; nb < 2; ++nb) {
                uint32_t addr = bbs + (b_base + (uint32_t)(nb * 16 * 72 + ks * 16)) * 2;
                asm volatile("ldmatrix.sync.aligned.m8n8.x4.shared.b16 {%0,%1,%2,%3}, [%4];"
                             : "=r"(bf[2 * nb][0]), "=r"(bf[2 * nb][1]),
                               "=r"(bf[2 * nb + 1][0]), "=r"(bf[2 * nb + 1][1])
                             : "r"(addr));
            }
#pragma unroll
            for (int mi = 0; mi < 4; ++mi)
#pragma unroll
                for (int ni = 0; ni < 4; ++ni) {
                    asm volatile(
                        "mma.sync.aligned.m16n8k16.row.col.f32.f16.f16.f32 "
                        "{%0,%1,%2,%3}, {%4,%5,%6,%7}, {%8,%9}, {%0,%1,%2,%3};"
                        : "+f"(acc[mi][ni][0]), "+f"(acc[mi][ni][1]),
                          "+f"(acc[mi][ni][2]), "+f"(acc[mi][ni][3])
                        : "r"(af[mi][0]), "r"(af[mi][1]), "r"(af[mi][2]), "r"(af[mi][3]),
                          "r"(bf[ni][0]), "r"(bf[ni][1]));
                }
        }
        __syncthreads();
    }

    const int rb = row0 + wm * 64 + (lane >> 2);
    const int cb = col0 + wn * 32 + (lane & 3) * 2;
#pragma unroll
    for (int mi = 0; mi < 4; ++mi)
#pragma unroll
        for (int ni = 0; ni < 4; ++ni) {
            int r = rb + mi * 16, cc = cb + ni * 8;
            *(float2*)(C + (size_t)r * ldc + cc) = make_float2(acc[mi][ni][0], acc[mi][ni][1]);
            *(float2*)(C + (size_t)(r + 8) * ldc + cc) =
                make_float2(acc[mi][ni][2], acc[mi][ni][3]);
        }
}

// ---------------------------------------------------------------------------
// fp32 -> 2-term fp16 split: out[m] = [hi(1024) | lo(1024)]  (exact to 22 bits)
// ---------------------------------------------------------------------------
__global__ __launch_bounds__(256) void convert_split2(const float* __restrict__ in,
                                                      __half* __restrict__ out) {
    size_t i = (size_t)blockIdx.x * 256 + threadIdx.x;   // float4 group id
    float4 v = ((const float4*)in)[i];
    size_t m = i >> 8;
    int k4 = (int)(i & 255) << 2;
    __half h0 = __float2half(v.x), h1 = __float2half(v.y);
    __half h2 = __float2half(v.z), h3 = __float2half(v.w);
    __half l0 = __float2half(v.x - __half2float(h0));
    __half l1 = __float2half(v.y - __half2float(h1));
    __half l2 = __float2half(v.z - __half2float(h2));
    __half l3 = __float2half(v.w - __half2float(h3));
    __half2* oh = (__half2*)(out + m * KP + k4);
    oh[0] = __halves2half2(h0, h1);
    oh[1] = __halves2half2(h2, h3);
    __half2* ol = (__half2*)(out + m * KP + 1024 + k4);
    ol[0] = __halves2half2(l0, l1);
    ol[1] = __halves2half2(l2, l3);
}

// W[1024][1024] fp32 -> B'[n][2048] = [hi | hi]  (transposed, K-major)
__global__ __launch_bounds__(256) void transpose_split2(const float* __restrict__ W,
                                                        __half* __restrict__ out) {
    __shared__ float s[32][33];
    const int tx = threadIdx.x & 31, ty = threadIdx.x >> 5;
    const int k0 = blockIdx.y << 5, n0 = blockIdx.x << 5;
#pragma unroll
    for (int r = 0; r < 32; r += 8)
        s[ty + r][tx] = W[(size_t)(k0 + ty + r) * 1024 + n0 + tx];
    __syncthreads();
#pragma unroll
    for (int r = 0; r < 32; r += 8) {
        const int n = n0 + ty + r, k = k0 + tx;
        __half h = __float2half(s[tx][ty + r]);
        out[(size_t)n * KP + k] = h;
        out[(size_t)n * KP + 1024 + k] = h;
    }
}

// Wa/Wb [1024][16] -> Wt32[32][1024] fp32
__global__ __launch_bounds__(256) void gates_prep32(const float* __restrict__ Wa,
                                                    const float* __restrict__ Wb,
                                                    float* __restrict__ out) {
    const int o = blockIdx.x;
    const float* W = (o < 16) ? Wa : Wb;
    const int h = o & 15;
    for (int k = threadIdx.x; k < 1024; k += 256)
        out[(size_t)o * 1024 + k] = W[k * 16 + h];
}

// ---------------------------------------------------------------------------
// Gates: logits = x @ Wt32^T, + bias, sigmoid. Block = 64 rows x 32 outputs.
// ---------------------------------------------------------------------------
__global__ __launch_bounds__(256) void gates64(const float* __restrict__ x,
                                               const float* __restrict__ Wt,
                                               const float* __restrict__ ba,
                                               const float* __restrict__ bb,
                                               float* __restrict__ alpha,
                                               float* __restrict__ beta) {
    __shared__ float xs[64][64];
    __shared__ float ws[32][65];
    const int tid = threadIdx.x;
    const int row0 = blockIdx.x * 64;
    const int rg = tid >> 5;
    const int o = tid & 31;

    float acc[8];
#pragma unroll
    for (int p = 0; p < 8; ++p) acc[p] = 0.f;

    for (int kc = 0; kc < 16; ++kc) {
        __syncthreads();
#pragma unroll
        for (int l = 0; l < 4; ++l) {
            int idx = tid + (l << 8);
            int r = idx >> 4, q = idx & 15;
            float4 v = *(const float4*)(x + (size_t)(row0 + r) * 1024 + kc * 64 + q * 4);
            *(float4*)(&xs[r][q * 4]) = v;
        }
#pragma unroll
        for (int l = 0; l < 2; ++l) {
            int idx = tid + (l << 8);
            int r = idx >> 4, q = idx & 15;
            float4 v = *(const float4*)(Wt + (size_t)r * 1024 + kc * 64 + q * 4);
            ws[r][q * 4 + 0] = v.x; ws[r][q * 4 + 1] = v.y;
            ws[r][q * 4 + 2] = v.z; ws[r][q * 4 + 3] = v.w;
        }
        __syncthreads();
#pragma unroll 8
        for (int k = 0; k < 64; ++k) {
            float wv = ws[o][k];
#pragma unroll
            for (int p = 0; p < 8; ++p)
                acc[p] = fmaf(xs[rg * 8 + p][k], wv, acc[p]);
        }
    }

    const float bias = (o < 16) ? ba[o] : bb[o - 16];
#pragma unroll
    for (int p = 0; p < 8; ++p) {
        float r = 1.f / (1.f + expf(-(acc[p] + bias)));
        int row = row0 + rg * 8 + p;
        if (o < 16) alpha[(size_t)row * 16 + o] = r;
        else        beta[(size_t)row * 16 + (o - 16)] = r;
    }
}

// ---------------------------------------------------------------------------
// K normalize over fused QKV buffer (K = cols [1024,2048))
// ---------------------------------------------------------------------------
__global__ __launch_bounds__(256) void knorm2(float* __restrict__ QKV) {
    const int w = (int)((blockIdx.x * blockDim.x + threadIdx.x) >> 5);
    const int lane = threadIdx.x & 31;
    if (w >= NROWS * H_) return;
    const int n = w >> 4, h = w & 15;
    float2* p = (float2*)(QKV + (size_t)n * 3072 + 1024 + h * 64);
    float2 v = p[lane];
    float ss = v.x * v.x + v.y * v.y;
#pragma unroll
    for (int m = 16; m; m >>= 1) ss += __shfl_xor_sync(~0u, ss, m);
    float inv = 1.f / fmaxf(sqrtf(ss), 1e-12f);
    v.x *= inv; v.y *= inv;
    p[lane] = v;
}

// ---------------------------------------------------------------------------
// Sequential scan: 128 blocks (one per (b,h,row-half)), 128 threads.
// ---------------------------------------------------------------------------
__global__ __launch_bounds__(128) void scan_kernel2(
    const float* __restrict__ QKV, const float* __restrict__ alpha,
    const float* __restrict__ beta, const float* __restrict__ S0,
    float* __restrict__ Y, float* __restrict__ Sout) {
    constexpr int CH = 16;
    __shared__ float cq[2][CH][64];
    __shared__ float ck[2][CH][64];
    __shared__ float cv[2][CH][32];
    __shared__ float ca[2][CH];
    __shared__ float cb[2][CH];

    const int tid = threadIdx.x;
    const int bh2 = blockIdx.x;
    const int bh = bh2 >> 1, half = bh2 & 1;
    const int b = bh >> 4, h = bh & 15;
    const int i = tid >> 2;
    const int gi = half * 32 + i;
    const int jg = tid & 3;
    const int j0 = jg << 4;

    float4 s4[4];
    {
        const float4* sp = (const float4*)(S0 + ((size_t)bh * 64 + gi) * 64 + j0);
        s4[0] = sp[0]; s4[1] = sp[1]; s4[2] = sp[2]; s4[3] = sp[3];
    }

    const float* rowQ = QKV + (size_t)b * T_ * 3072 + (size_t)h * 64;

    auto load_chunk = [&](int t0, int buf) {
#pragma unroll
        for (int l = 0; l < 2; ++l) {
            int idx = tid + (l << 7);
            int st = idx >> 4, f = (idx & 15) << 2;
            const float* base = rowQ + (size_t)(t0 + st) * 3072;
            *(float4*)(&cq[buf][st][f]) = *(const float4*)(base + f);
            *(float4*)(&ck[buf][st][f]) = *(const float4*)(base + 1024 + f);
        }
        {
            int st = tid >> 3, f = (tid & 7) << 2;
            const float* base = rowQ + (size_t)(t0 + st) * 3072 + 2048 + half * 32;
            *(float4*)(&cv[buf][st][f]) = *(const float4*)(base + f);
        }
        if (tid < CH)
            ca[buf][tid] = alpha[((size_t)b * T_ + t0 + tid) * H_ + h];
        else if (tid < 2 * CH)
            cb[buf][tid - CH] = beta[((size_t)b * T_ + t0 + tid - CH) * H_ + h];
    };

    const size_t ybase = (size_t)b * T_ * DM_ + (size_t)h * 64 + gi;
    const int nch = T_ / CH;
    load_chunk(0, 0);
    __syncthreads();

    for (int c = 0; c < nch; ++c) {
        const int buf = c & 1;
        if (c + 1 < nch) load_chunk((c + 1) * CH, buf ^ 1);

#pragma unroll 4
        for (int s = 0; s < CH; ++s) {
            const float a = ca[buf][s];
            const float bg = cb[buf][s];
            const float bv = bg * cv[buf][s][i];
            const float4* kp = (const float4*)(&ck[buf][s][j0]);
            const float4* qp = (const float4*)(&cq[buf][s][j0]);
            float partial = 0.f;
#pragma unroll
            for (int v = 0; v < 4; ++v) {
                float4 kk = kp[v];
                float4 qq = qp[v];
                s4[v].x = fmaf(a, s4[v].x, bv * kk.x); partial = fmaf(s4[v].x, qq.x, partial);
                s4[v].y = fmaf(a, s4[v].y, bv * kk.y); partial = fmaf(s4[v].y, qq.y, partial);
                s4[v].z = fmaf(a, s4[v].z, bv * kk.z); partial = fmaf(s4[v].z, qq.z, partial);
                s4[v].w = fmaf(a, s4[v].w, bv * kk.w); partial = fmaf(s4[v].w, qq.w, partial);
            }
            partial += __shfl_xor_sync(~0u, partial, 1);
            partial += __shfl_xor_sync(~0u, partial, 2);
            if (jg == 0)
                Y[ybase + (size_t)(c * CH + s) * DM_] = partial;
        }
        __syncthreads();
    }

    float4* so = (float4*)(Sout + ((size_t)bh * 64 + gi) * 64 + j0);
    so[0] = s4[0]; so[1] = s4[1]; so[2] = s4[2]; so[3] = s4[3];
}

// ---------------------------------------------------------------------------
extern "C" void kernel_launch(void* const* d_in, const int* in_sizes, int n_in,
                              void* d_out, int out_size) {
    (void)in_sizes; (void)n_in;
    const float* x  = (const float*)d_in[0];
    const float* S0 = (const float*)d_in[1];
    const float* Wq = (const float*)d_in[2];
    const float* Wk = (const float*)d_in[3];
    const float* Wv = (const float*)d_in[4];
    const float* Wa = (const float*)d_in[5];
    const float* ba = (const float*)d_in[6];
    const float* Wb = (const float*)d_in[7];
    const float* bb = (const float*)d_in[8];
    const float* Wo = (const float*)d_in[9];
    float* out = (float*)d_out;

    float *QKVd, *Yd, *al, *be, *Sdump, *Wab32;
    __half *A2, *Y2, *Wqkv, *Wto;
    cudaGetSymbolAddress((void**)&QKVd, g_QKV);
    cudaGetSymbolAddress((void**)&Yd, g_Y);
    cudaGetSymbolAddress((void**)&al, g_alpha);
    cudaGetSymbolAddress((void**)&be, g_beta);
    cudaGetSymbolAddress((void**)&Sdump, g_Sdump);
    cudaGetSymbolAddress((void**)&Wab32, g_Wab32);
    cudaGetSymbolAddress((void**)&A2, g_A2);
    cudaGetSymbolAddress((void**)&Y2, g_Y2);
    cudaGetSymbolAddress((void**)&Wqkv, g_Wqkv);
    cudaGetSymbolAddress((void**)&Wto, g_Wto);

    float* Sout = (out_size >= NROWS * DM_ + STATE_ELEMS) ? out + (size_t)NROWS * DM_ : Sdump;

    constexpr int GSMEM = 2 * 36864;   // 73728 per CTA (2-stage)
    cudaFuncSetAttribute(gemm_mma, cudaFuncAttributeMaxDynamicSharedMemorySize, GSMEM);

    convert_split2<<<NROWS, 256>>>(x, A2);
    transpose_split2<<<dim3(32, 32), 256>>>(Wq, Wqkv);
    transpose_split2<<<dim3(32, 32), 256>>>(Wk, Wqkv + (size_t)1024 * KP);
    transpose_split2<<<dim3(32, 32), 256>>>(Wv, Wqkv + (size_t)2048 * KP);
    gates_prep32<<<32, 256>>>(Wa, Wb, Wab32);
    gemm_mma<<<dim3(3072 / 128, NROWS / 128), 256, GSMEM>>>(A2, Wqkv, QKVd, 3072);
    gates64<<<NROWS / 64, 256>>>(x, Wab32, ba, bb, al, be);
    knorm2<<<(NROWS * H_ * 32) / 256, 256>>>(QKVd);
    scan_kernel2<<<128, 128>>>(QKVd, al, be, S0, Yd, Sout);
    convert_split2<<<NROWS, 256>>>(Yd, Y2);
    transpose_split2<<<dim3(32, 32), 256>>>(Wo, Wto);
    gemm_mma<<<dim3(1024 / 128, NROWS / 128), 256, GSMEM>>>(Y2, Wto, out, 1024);
}

// round 11
// speedup vs baseline: 2.9125x; 1.2536x over previous
#include <cuda_runtime.h>
#include <cuda_fp16.h>
#include <cstdint>
#include <math.h>

// Problem dims
constexpr int B_ = 4, T_ = 2048, DM_ = 1024, H_ = 16, D_ = 64;
constexpr int NROWS = B_ * T_;           // 8192
constexpr int KP = 1024;                 // plain fp16 GEMM (no split)
constexpr int STATE_ELEMS = B_ * H_ * D_ * D_;

// ---------------- scratch (device globals; allocation-free) ----------------
__device__ float g_QKV[(size_t)NROWS * 3072];   // fused Q|K|V fp32
__device__ float g_Y[(size_t)NROWS * DM_];
__device__ float g_alpha[NROWS * H_];
__device__ float g_beta[NROWS * H_];
__device__ float g_Sdump[STATE_ELEMS];
__device__ float g_Wab32[32 * DM_];
__device__ __half g_A2[(size_t)NROWS * KP];
__device__ __half g_Y2[(size_t)NROWS * KP];
__device__ __half g_Wqkv[(size_t)3072 * KP];   // rows: Wq|Wk|Wv output cols
__device__ __half g_Wto[(size_t)DM_ * KP];

// ---------------------------------------------------------------------------
// fp16 mma.sync GEMM: C[8192, N] = A[8192,1024]f16 @ B[N,1024]f16^T
// R4/R10-proven structure: CTA 128x128, 8 warps (2M x 4N), warp tile 64x32,
// Kc=64, double-buffered cp.async, 2 CTAs/SM. smem rows padded to 72 halves
// (144B), conflict-free.
// ---------------------------------------------------------------------------
__global__ __launch_bounds__(256, 2) void gemm_mma(const __half* __restrict__ A,
                                                   const __half* __restrict__ Bw,
                                                   float* __restrict__ C, int ldc) {
    extern __shared__ char sm[];
    const int tid = threadIdx.x;
    const int lane = tid & 31, wid = tid >> 5;
    const int wm = wid & 1, wn = wid >> 1;       // 2 x 4 warp grid
    const int row0 = blockIdx.y * 128;
    const int col0 = blockIdx.x * 128;

    uint32_t sb;
    asm("{ .reg .u64 t; cvta.to.shared.u64 t, %1; cvt.u32.u64 %0, t; }" : "=r"(sb) : "l"(sm));

    // per-stage: A 128*72*2 = 18432 B, B same. stage = 36864; two stages.
    const uint32_t A_OFF[2] = {0u, 36864u};
    const uint32_t B_OFF[2] = {18432u, 36864u + 18432u};

    float acc[4][4][4];
#pragma unroll
    for (int i = 0; i < 4; ++i)
#pragma unroll
        for (int j = 0; j < 4; ++j)
#pragma unroll
            for (int q = 0; q < 4; ++q) acc[i][j][q] = 0.f;

    auto load_chunk = [&](int c, int buf) {
        const __half* gA = A + (size_t)row0 * KP + c * 64;
        uint32_t ab = sb + A_OFF[buf];
#pragma unroll
        for (int l = 0; l < 4; ++l) {
            int idx = tid + (l << 8);
            int r = idx >> 3, s = idx & 7;
            uint32_t so = ab + (uint32_t)(r * 144 + s * 16);
            const void* gp = gA + (size_t)r * KP + s * 8;
            asm volatile("cp.async.cg.shared.global [%0], [%1], 16;" :: "r"(so), "l"(gp));
        }
        const __half* gB = Bw + (size_t)col0 * KP + c * 64;
        uint32_t bbx = sb + B_OFF[buf];
#pragma unroll
        for (int l = 0; l < 4; ++l) {
            int idx = tid + (l << 8);
            int n = idx >> 3, s = idx & 7;
            uint32_t so = bbx + (uint32_t)(n * 144 + s * 16);
            const void* gp = gB + (size_t)n * KP + s * 8;
            asm volatile("cp.async.cg.shared.global [%0], [%1], 16;" :: "r"(so), "l"(gp));
        }
        asm volatile("cp.async.commit_group;" ::: "memory");
    };

    // per-lane ldmatrix base offsets (halves); pad-72 addressing from R4
    const uint32_t a_base = (uint32_t)((wm * 64 + (lane & 15)) * 72 + ((lane >> 4) << 3));
    const uint32_t b_base = (uint32_t)((wn * 32 + (((lane >> 4) & 1) << 3) + (lane & 7)) * 72 +
                                       (((lane >> 3) & 1) << 3));

    load_chunk(0, 0);

    constexpr int NCH = KP / 64;  // 16
    for (int c = 0; c < NCH; ++c) {
        const int buf = c & 1;
        if (c + 1 < NCH) {
            load_chunk(c + 1, buf ^ 1);
            asm volatile("cp.async.wait_group 1;" ::: "memory");
        } else {
            asm volatile("cp.async.wait_group 0;" ::: "memory");
        }
        __syncthreads();

        const uint32_t ab = sb + A_OFF[buf];
        const uint32_t bbs = sb + B_OFF[buf];
#pragma unroll
        for (int ks = 0; ks < 4; ++ks) {
            uint32_t af[4][4];
#pragma unroll
            for (int mi = 0; mi < 4; ++mi) {
                uint32_t addr = ab + (a_base + (uint32_t)(mi * 16 * 72 + ks * 16)) * 2;
                asm volatile("ldmatrix.sync.aligned.m8n8.x4.shared.b16 {%0,%1,%2,%3}, [%4];"
                             : "=r"(af[mi][0]), "=r"(af[mi][1]), "=r"(af[mi][2]), "=r"(af[mi][3])
                             : "r"(addr));
            }
            uint32_t bf[4][2];
#pragma unroll
            for (int nb = 0; nb < 2; ++nb) {
                uint32_t addr = bbs + (b_base + (uint32_t)(nb * 16 * 72 + ks * 16)) * 2;
                asm volatile("ldmatrix.sync.aligned.m8n8.x4.shared.b16 {%0,%1,%2,%3}, [%4];"
                             : "=r"(bf[2 * nb][0]), "=r"(bf[2 * nb][1]),
                               "=r"(bf[2 * nb + 1][0]), "=r"(bf[2 * nb + 1][1])
                             : "r"(addr));
            }
#pragma unroll
            for (int mi = 0; mi < 4; ++mi)
#pragma unroll
                for (int ni = 0; ni < 4; ++ni) {
                    asm volatile(
                        "mma.sync.aligned.m16n8k16.row.col.f32.f16.f16.f32 "
                        "{%0,%1,%2,%3}, {%4,%5,%6,%7}, {%8,%9}, {%0,%1,%2,%3};"
                        : "+f"(acc[mi][ni][0]), "+f"(acc[mi][ni][1]),
                          "+f"(acc[mi][ni][2]), "+f"(acc[mi][ni][3])
                        : "r"(af[mi][0]), "r"(af[mi][1]), "r"(af[mi][2]), "r"(af[mi][3]),
                          "r"(bf[ni][0]), "r"(bf[ni][1]));
                }
        }
        __syncthreads();
    }

    const int rb = row0 + wm * 64 + (lane >> 2);
    const int cb = col0 + wn * 32 + (lane & 3) * 2;
#pragma unroll
    for (int mi = 0; mi < 4; ++mi)
#pragma unroll
        for (int ni = 0; ni < 4; ++ni) {
            int r = rb + mi * 16, cc = cb + ni * 8;
            *(float2*)(C + (size_t)r * ldc + cc) = make_float2(acc[mi][ni][0], acc[mi][ni][1]);
            *(float2*)(C + (size_t)(r + 8) * ldc + cc) =
                make_float2(acc[mi][ni][2], acc[mi][ni][3]);
        }
}

// ---------------------------------------------------------------------------
// fp32 -> fp16 flat cast (1 row per block, 256 threads x float4)
// ---------------------------------------------------------------------------
__global__ __launch_bounds__(256) void convert16(const float* __restrict__ in,
                                                 __half* __restrict__ out) {
    size_t i = (size_t)blockIdx.x * 256 + threadIdx.x;   // float4 group id
    float4 v = ((const float4*)in)[i];
    __half2 a = __halves2half2(__float2half(v.x), __float2half(v.y));
    __half2 b = __halves2half2(__float2half(v.z), __float2half(v.w));
    __half2* o = (__half2*)out + i * 2;
    o[0] = a;
    o[1] = b;
}

// W[1024][1024] fp32 -> Wt[n][1024] fp16 (transposed, K-major)
__global__ __launch_bounds__(256) void transpose16(const float* __restrict__ W,
                                                   __half* __restrict__ out) {
    __shared__ float s[32][33];
    const int tx = threadIdx.x & 31, ty = threadIdx.x >> 5;
    const int k0 = blockIdx.y << 5, n0 = blockIdx.x << 5;
#pragma unroll
    for (int r = 0; r < 32; r += 8)
        s[ty + r][tx] = W[(size_t)(k0 + ty + r) * 1024 + n0 + tx];
    __syncthreads();
#pragma unroll
    for (int r = 0; r < 32; r += 8) {
        const int n = n0 + ty + r, k = k0 + tx;
        out[(size_t)n * KP + k] = __float2half(s[tx][ty + r]);
    }
}

// Wa/Wb [1024][16] -> Wt32[32][1024] fp32
__global__ __launch_bounds__(256) void gates_prep32(const float* __restrict__ Wa,
                                                    const float* __restrict__ Wb,
                                                    float* __restrict__ out) {
    const int o = blockIdx.x;
    const float* W = (o < 16) ? Wa : Wb;
    const int h = o & 15;
    for (int k = threadIdx.x; k < 1024; k += 256)
        out[(size_t)o * 1024 + k] = W[k * 16 + h];
}

// ---------------------------------------------------------------------------
// Gates: logits = x @ Wt32^T, + bias, sigmoid. Block = 64 rows x 32 outputs.
// ---------------------------------------------------------------------------
__global__ __launch_bounds__(256) void gates64(const float* __restrict__ x,
                                               const float* __restrict__ Wt,
                                               const float* __restrict__ ba,
                                               const float* __restrict__ bb,
                                               float* __restrict__ alpha,
                                               float* __restrict__ beta) {
    __shared__ float xs[64][64];
    __shared__ float ws[32][65];
    const int tid = threadIdx.x;
    const int row0 = blockIdx.x * 64;
    const int rg = tid >> 5;
    const int o = tid & 31;

    float acc[8];
#pragma unroll
    for (int p = 0; p < 8; ++p) acc[p] = 0.f;

    for (int kc = 0; kc < 16; ++kc) {
        __syncthreads();
#pragma unroll
        for (int l = 0; l < 4; ++l) {
            int idx = tid + (l << 8);
            int r = idx >> 4, q = idx & 15;
            float4 v = *(const float4*)(x + (size_t)(row0 + r) * 1024 + kc * 64 + q * 4);
            *(float4*)(&xs[r][q * 4]) = v;
        }
#pragma unroll
        for (int l = 0; l < 2; ++l) {
            int idx = tid + (l << 8);
            int r = idx >> 4, q = idx & 15;
            float4 v = *(const float4*)(Wt + (size_t)r * 1024 + kc * 64 + q * 4);
            ws[r][q * 4 + 0] = v.x; ws[r][q * 4 + 1] = v.y;
            ws[r][q * 4 + 2] = v.z; ws[r][q * 4 + 3] = v.w;
        }
        __syncthreads();
#pragma unroll 8
        for (int k = 0; k < 64; ++k) {
            float wv = ws[o][k];
#pragma unroll
            for (int p = 0; p < 8; ++p)
                acc[p] = fmaf(xs[rg * 8 + p][k], wv, acc[p]);
        }
    }

    const float bias = (o < 16) ? ba[o] : bb[o - 16];
#pragma unroll
    for (int p = 0; p < 8; ++p) {
        float r = 1.f / (1.f + expf(-(acc[p] + bias)));
        int row = row0 + rg * 8 + p;
        if (o < 16) alpha[(size_t)row * 16 + o] = r;
        else        beta[(size_t)row * 16 + (o - 16)] = r;
    }
}

// ---------------------------------------------------------------------------
// K normalize over fused QKV buffer (K = cols [1024,2048))
// ---------------------------------------------------------------------------
__global__ __launch_bounds__(256) void knorm2(float* __restrict__ QKV) {
    const int w = (int)((blockIdx.x * blockDim.x + threadIdx.x) >> 5);
    const int lane = threadIdx.x & 31;
    if (w >= NROWS * H_) return;
    const int n = w >> 4, h = w & 15;
    float2* p = (float2*)(QKV + (size_t)n * 3072 + 1024 + h * 64);
    float2 v = p[lane];
    float ss = v.x * v.x + v.y * v.y;
#pragma unroll
    for (int m = 16; m; m >>= 1) ss += __shfl_xor_sync(~0u, ss, m);
    float inv = 1.f / fmaxf(sqrtf(ss), 1e-12f);
    v.x *= inv; v.y *= inv;
    p[lane] = v;
}

// ---------------------------------------------------------------------------
// Sequential scan: 128 blocks (one per (b,h,row-half)), 128 threads.
// ---------------------------------------------------------------------------
__global__ __launch_bounds__(128) void scan_kernel2(
    const float* __restrict__ QKV, const float* __restrict__ alpha,
    const float* __restrict__ beta, const float* __restrict__ S0,
    float* __restrict__ Y, float* __restrict__ Sout) {
    constexpr int CH = 16;
    __shared__ float cq[2][CH][64];
    __shared__ float ck[2][CH][64];
    __shared__ float cv[2][CH][32];
    __shared__ float ca[2][CH];
    __shared__ float cb[2][CH];

    const int tid = threadIdx.x;
    const int bh2 = blockIdx.x;
    const int bh = bh2 >> 1, half = bh2 & 1;
    const int b = bh >> 4, h = bh & 15;
    const int i = tid >> 2;
    const int gi = half * 32 + i;
    const int jg = tid & 3;
    const int j0 = jg << 4;

    float4 s4[4];
    {
        const float4* sp = (const float4*)(S0 + ((size_t)bh * 64 + gi) * 64 + j0);
        s4[0] = sp[0]; s4[1] = sp[1]; s4[2] = sp[2]; s4[3] = sp[3];
    }

    const float* rowQ = QKV + (size_t)b * T_ * 3072 + (size_t)h * 64;

    auto load_chunk = [&](int t0, int buf) {
#pragma unroll
        for (int l = 0; l < 2; ++l) {
            int idx = tid + (l << 7);
            int st = idx >> 4, f = (idx & 15) << 2;
            const float* base = rowQ + (size_t)(t0 + st) * 3072;
            *(float4*)(&cq[buf][st][f]) = *(const float4*)(base + f);
            *(float4*)(&ck[buf][st][f]) = *(const float4*)(base + 1024 + f);
        }
        {
            int st = tid >> 3, f = (tid & 7) << 2;
            const float* base = rowQ + (size_t)(t0 + st) * 3072 + 2048 + half * 32;
            *(float4*)(&cv[buf][st][f]) = *(const float4*)(base + f);
        }
        if (tid < CH)
            ca[buf][tid] = alpha[((size_t)b * T_ + t0 + tid) * H_ + h];
        else if (tid < 2 * CH)
            cb[buf][tid - CH] = beta[((size_t)b * T_ + t0 + tid - CH) * H_ + h];
    };

    const size_t ybase = (size_t)b * T_ * DM_ + (size_t)h * 64 + gi;
    const int nch = T_ / CH;
    load_chunk(0, 0);
    __syncthreads();

    for (int c = 0; c < nch; ++c) {
        const int buf = c & 1;
        if (c + 1 < nch) load_chunk((c + 1) * CH, buf ^ 1);

#pragma unroll 4
        for (int s = 0; s < CH; ++s) {
            const float a = ca[buf][s];
            const float bg = cb[buf][s];
            const float bv = bg * cv[buf][s][i];
            const float4* kp = (const float4*)(&ck[buf][s][j0]);
            const float4* qp = (const float4*)(&cq[buf][s][j0]);
            float partial = 0.f;
#pragma unroll
            for (int v = 0; v < 4; ++v) {
                float4 kk = kp[v];
                float4 qq = qp[v];
                s4[v].x = fmaf(a, s4[v].x, bv * kk.x); partial = fmaf(s4[v].x, qq.x, partial);
                s4[v].y = fmaf(a, s4[v].y, bv * kk.y); partial = fmaf(s4[v].y, qq.y, partial);
                s4[v].z = fmaf(a, s4[v].z, bv * kk.z); partial = fmaf(s4[v].z, qq.z, partial);
                s4[v].w = fmaf(a, s4[v].w, bv * kk.w); partial = fmaf(s4[v].w, qq.w, partial);
            }
            partial += __shfl_xor_sync(~0u, partial, 1);
            partial += __shfl_xor_sync(~0u, partial, 2);
            if (jg == 0)
                Y[ybase + (size_t)(c * CH + s) * DM_] = partial;
        }
        __syncthreads();
    }

    float4* so = (float4*)(Sout + ((size_t)bh * 64 + gi) * 64 + j0);
    so[0] = s4[0]; so[1] = s4[1]; so[2] = s4[2]; so[3] = s4[3];
}

// ---------------------------------------------------------------------------
extern "C" void kernel_launch(void* const* d_in, const int* in_sizes, int n_in,
                              void* d_out, int out_size) {
    (void)in_sizes; (void)n_in;
    const float* x  = (const float*)d_in[0];
    const float* S0 = (const float*)d_in[1];
    const float* Wq = (const float*)d_in[2];
    const float* Wk = (const float*)d_in[3];
    const float* Wv = (const float*)d_in[4];
    const float* Wa = (const float*)d_in[5];
    const float* ba = (const float*)d_in[6];
    const float* Wb = (const float*)d_in[7];
    const float* bb = (const float*)d_in[8];
    const float* Wo = (const float*)d_in[9];
    float* out = (float*)d_out;

    float *QKVd, *Yd, *al, *be, *Sdump, *Wab32;
    __half *A2, *Y2, *Wqkv, *Wto;
    cudaGetSymbolAddress((void**)&QKVd, g_QKV);
    cudaGetSymbolAddress((void**)&Yd, g_Y);
    cudaGetSymbolAddress((void**)&al, g_alpha);
    cudaGetSymbolAddress((void**)&be, g_beta);
    cudaGetSymbolAddress((void**)&Sdump, g_Sdump);
    cudaGetSymbolAddress((void**)&Wab32, g_Wab32);
    cudaGetSymbolAddress((void**)&A2, g_A2);
    cudaGetSymbolAddress((void**)&Y2, g_Y2);
    cudaGetSymbolAddress((void**)&Wqkv, g_Wqkv);
    cudaGetSymbolAddress((void**)&Wto, g_Wto);

    float* Sout = (out_size >= NROWS * DM_ + STATE_ELEMS) ? out + (size_t)NROWS * DM_ : Sdump;

    constexpr int GSMEM = 2 * 36864;   // 73728 per CTA (2-stage)
    cudaFuncSetAttribute(gemm_mma, cudaFuncAttributeMaxDynamicSharedMemorySize, GSMEM);

    convert16<<<NROWS, 256>>>(x, A2);
    transpose16<<<dim3(32, 32), 256>>>(Wq, Wqkv);
    transpose16<<<dim3(32, 32), 256>>>(Wk, Wqkv + (size_t)1024 * KP);
    transpose16<<<dim3(32, 32), 256>>>(Wv, Wqkv + (size_t)2048 * KP);
    gates_prep32<<<32, 256>>>(Wa, Wb, Wab32);
    gemm_mma<<<dim3(3072 / 128, NROWS / 128), 256, GSMEM>>>(A2, Wqkv, QKVd, 3072);
    gates64<<<NROWS / 64, 256>>>(x, Wab32, ba, bb, al, be);
    knorm2<<<(NROWS * H_ * 32) / 256, 256>>>(QKVd);
    scan_kernel2<<<128, 128>>>(QKVd, al, be, S0, Yd, Sout);
    convert16<<<NROWS, 256>>>(Yd, Y2);
    transpose16<<<dim3(32, 32), 256>>>(Wo, Wto);
    gemm_mma<<<dim3(1024 / 128, NROWS / 128), 256, GSMEM>>>(Y2, Wto, out, 1024);
}

// round 13
// speedup vs baseline: 3.3939x; 1.1653x over previous
#include <cuda_runtime.h>
#include <cuda_fp16.h>
#include <cstdint>
#include <math.h>

// Problem dims
constexpr int B_ = 4, T_ = 2048, DM_ = 1024, H_ = 16, D_ = 64;
constexpr int NROWS = B_ * T_;           // 8192
constexpr int KP = 1024;                 // plain fp16 GEMM (no split)
constexpr int STATE_ELEMS = B_ * H_ * D_ * D_;

// ---------------- scratch (device globals; allocation-free) ----------------
__device__ float g_QKV[(size_t)NROWS * 3072];   // fused Q|K|V fp32
__device__ float g_alpha[NROWS * H_];
__device__ float g_beta[NROWS * H_];
__device__ float g_Sdump[STATE_ELEMS];
__device__ float g_Wab32[32 * DM_];
__device__ __half g_A2[(size_t)NROWS * KP];
__device__ __half g_Y2[(size_t)NROWS * KP];     // scan writes fp16 directly
__device__ __half g_Wqkv[(size_t)3072 * KP];    // rows: Wq|Wk|Wv output cols
__device__ __half g_Wto[(size_t)DM_ * KP];

// ---------------------------------------------------------------------------
// fp16 mma.sync GEMM: C[8192, N] = A[8192,1024]f16 @ B[N,1024]f16^T
// R4/R10-proven structure: CTA 128x128, 8 warps (2M x 4N), warp tile 64x32,
// Kc=64, double-buffered cp.async, 2 CTAs/SM. smem rows padded to 72 halves
// (144B), conflict-free.
// ---------------------------------------------------------------------------
__global__ __launch_bounds__(256, 2) void gemm_mma(const __half* __restrict__ A,
                                                   const __half* __restrict__ Bw,
                                                   float* __restrict__ C, int ldc) {
    extern __shared__ char sm[];
    const int tid = threadIdx.x;
    const int lane = tid & 31, wid = tid >> 5;
    const int wm = wid & 1, wn = wid >> 1;       // 2 x 4 warp grid
    const int row0 = blockIdx.y * 128;
    const int col0 = blockIdx.x * 128;

    uint32_t sb;
    asm("{ .reg .u64 t; cvta.to.shared.u64 t, %1; cvt.u32.u64 %0, t; }" : "=r"(sb) : "l"(sm));

    const uint32_t A_OFF[2] = {0u, 36864u};
    const uint32_t B_OFF[2] = {18432u, 36864u + 18432u};

    float acc[4][4][4];
#pragma unroll
    for (int i = 0; i < 4; ++i)
#pragma unroll
        for (int j = 0; j < 4; ++j)
#pragma unroll
            for (int q = 0; q < 4; ++q) acc[i][j][q] = 0.f;

    auto load_chunk = [&](int c, int buf) {
        const __half* gA = A + (size_t)row0 * KP + c * 64;
        uint32_t ab = sb + A_OFF[buf];
#pragma unroll
        for (int l = 0; l < 4; ++l) {
            int idx = tid + (l << 8);
            int r = idx >> 3, s = idx & 7;
            uint32_t so = ab + (uint32_t)(r * 144 + s * 16);
            const void* gp = gA + (size_t)r * KP + s * 8;
            asm volatile("cp.async.cg.shared.global [%0], [%1], 16;" :: "r"(so), "l"(gp));
        }
        const __half* gB = Bw + (size_t)col0 * KP + c * 64;
        uint32_t bbx = sb + B_OFF[buf];
#pragma unroll
        for (int l = 0; l < 4; ++l) {
            int idx = tid + (l << 8);
            int n = idx >> 3, s = idx & 7;
            uint32_t so = bbx + (uint32_t)(n * 144 + s * 16);
            const void* gp = gB + (size_t)n * KP + s * 8;
            asm volatile("cp.async.cg.shared.global [%0], [%1], 16;" :: "r"(so), "l"(gp));
        }
        asm volatile("cp.async.commit_group;" ::: "memory");
    };

    const uint32_t a_base = (uint32_t)((wm * 64 + (lane & 15)) * 72 + ((lane >> 4) << 3));
    const uint32_t b_base = (uint32_t)((wn * 32 + (((lane >> 4) & 1) << 3) + (lane & 7)) * 72 +
                                       (((lane >> 3) & 1) << 3));

    load_chunk(0, 0);

    constexpr int NCH = KP / 64;  // 16
    for (int c = 0; c < NCH; ++c) {
        const int buf = c & 1;
        if (c + 1 < NCH) {
            load_chunk(c + 1, buf ^ 1);
            asm volatile("cp.async.wait_group 1;" ::: "memory");
        } else {
            asm volatile("cp.async.wait_group 0;" ::: "memory");
        }
        __syncthreads();

        const uint32_t ab = sb + A_OFF[buf];
        const uint32_t bbs = sb + B_OFF[buf];
#pragma unroll
        for (int ks = 0; ks < 4; ++ks) {
            uint32_t af[4][4];
#pragma unroll
            for (int mi = 0; mi < 4; ++mi) {
                uint32_t addr = ab + (a_base + (uint32_t)(mi * 16 * 72 + ks * 16)) * 2;
                asm volatile("ldmatrix.sync.aligned.m8n8.x4.shared.b16 {%0,%1,%2,%3}, [%4];"
                             : "=r"(af[mi][0]), "=r"(af[mi][1]), "=r"(af[mi][2]), "=r"(af[mi][3])
                             : "r"(addr));
            }
            uint32_t bf[4][2];
#pragma unroll
            for (int nb = 0; nb < 2; ++nb) {
                uint32_t addr = bbs + (b_base + (uint32_t)(nb * 16 * 72 + ks * 16)) * 2;
                asm volatile("ldmatrix.sync.aligned.m8n8.x4.shared.b16 {%0,%1,%2,%3}, [%4];"
                             : "=r"(bf[2 * nb][0]), "=r"(bf[2 * nb][1]),
                               "=r"(bf[2 * nb + 1][0]), "=r"(bf[2 * nb + 1][1])
                             : "r"(addr));
            }
#pragma unroll
            for (int mi = 0; mi < 4; ++mi)
#pragma unroll
                for (int ni = 0; ni < 4; ++ni) {
                    asm volatile(
                        "mma.sync.aligned.m16n8k16.row.col.f32.f16.f16.f32 "
                        "{%0,%1,%2,%3}, {%4,%5,%6,%7}, {%8,%9}, {%0,%1,%2,%3};"
                        : "+f"(acc[mi][ni][0]), "+f"(acc[mi][ni][1]),
                          "+f"(acc[mi][ni][2]), "+f"(acc[mi][ni][3])
                        : "r"(af[mi][0]), "r"(af[mi][1]), "r"(af[mi][2]), "r"(af[mi][3]),
                          "r"(bf[ni][0]), "r"(bf[ni][1]));
                }
        }
        __syncthreads();
    }

    const int rb = row0 + wm * 64 + (lane >> 2);
    const int cb = col0 + wn * 32 + (lane & 3) * 2;
#pragma unroll
    for (int mi = 0; mi < 4; ++mi)
#pragma unroll
        for (int ni = 0; ni < 4; ++ni) {
            int r = rb + mi * 16, cc = cb + ni * 8;
            *(float2*)(C + (size_t)r * ldc + cc) = make_float2(acc[mi][ni][0], acc[mi][ni][1]);
            *(float2*)(C + (size_t)(r + 8) * ldc + cc) =
                make_float2(acc[mi][ni][2], acc[mi][ni][3]);
        }
}

// ---------------------------------------------------------------------------
// fp32 -> fp16 flat cast
// ---------------------------------------------------------------------------
__global__ __launch_bounds__(256) void convert16(const float* __restrict__ in,
                                                 __half* __restrict__ out) {
    size_t i = (size_t)blockIdx.x * 256 + threadIdx.x;
    float4 v = ((const float4*)in)[i];
    __half2 a = __halves2half2(__float2half(v.x), __float2half(v.y));
    __half2 b = __halves2half2(__float2half(v.z), __float2half(v.w));
    __half2* o = (__half2*)out + i * 2;
    o[0] = a;
    o[1] = b;
}

// W[1024][1024] fp32 -> Wt[n][1024] fp16 (transposed, K-major)
__global__ __launch_bounds__(256) void transpose16(const float* __restrict__ W,
                                                   __half* __restrict__ out) {
    __shared__ float s[32][33];
    const int tx = threadIdx.x & 31, ty = threadIdx.x >> 5;
    const int k0 = blockIdx.y << 5, n0 = blockIdx.x << 5;
#pragma unroll
    for (int r = 0; r < 32; r += 8)
        s[ty + r][tx] = W[(size_t)(k0 + ty + r) * 1024 + n0 + tx];
    __syncthreads();
#pragma unroll
    for (int r = 0; r < 32; r += 8) {
        const int n = n0 + ty + r, k = k0 + tx;
        out[(size_t)n * KP + k] = __float2half(s[tx][ty + r]);
    }
}

// Wa/Wb [1024][16] -> Wt32[32][1024] fp32
__global__ __launch_bounds__(256) void gates_prep32(const float* __restrict__ Wa,
                                                    const float* __restrict__ Wb,
                                                    float* __restrict__ out) {
    const int o = blockIdx.x;
    const float* W = (o < 16) ? Wa : Wb;
    const int h = o & 15;
    for (int k = threadIdx.x; k < 1024; k += 256)
        out[(size_t)o * 1024 + k] = W[k * 16 + h];
}

// ---------------------------------------------------------------------------
// Gates: logits = x @ Wt32^T, + bias, sigmoid. Block = 64 rows x 32 outputs.
// ---------------------------------------------------------------------------
__global__ __launch_bounds__(256) void gates64(const float* __restrict__ x,
                                               const float* __restrict__ Wt,
                                               const float* __restrict__ ba,
                                               const float* __restrict__ bb,
                                               float* __restrict__ alpha,
                                               float* __restrict__ beta) {
    __shared__ float xs[64][64];
    __shared__ float ws[32][65];
    const int tid = threadIdx.x;
    const int row0 = blockIdx.x * 64;
    const int rg = tid >> 5;
    const int o = tid & 31;

    float acc[8];
#pragma unroll
    for (int p = 0; p < 8; ++p) acc[p] = 0.f;

    for (int kc = 0; kc < 16; ++kc) {
        __syncthreads();
#pragma unroll
        for (int l = 0; l < 4; ++l) {
            int idx = tid + (l << 8);
            int r = idx >> 4, q = idx & 15;
            float4 v = *(const float4*)(x + (size_t)(row0 + r) * 1024 + kc * 64 + q * 4);
            *(float4*)(&xs[r][q * 4]) = v;
        }
#pragma unroll
        for (int l = 0; l < 2; ++l) {
            int idx = tid + (l << 8);
            int r = idx >> 4, q = idx & 15;
            float4 v = *(const float4*)(Wt + (size_t)r * 1024 + kc * 64 + q * 4);
            ws[r][q * 4 + 0] = v.x; ws[r][q * 4 + 1] = v.y;
            ws[r][q * 4 + 2] = v.z; ws[r][q * 4 + 3] = v.w;
        }
        __syncthreads();
#pragma unroll 8
        for (int k = 0; k < 64; ++k) {
            float wv = ws[o][k];
#pragma unroll
            for (int p = 0; p < 8; ++p)
                acc[p] = fmaf(xs[rg * 8 + p][k], wv, acc[p]);
        }
    }

    const float bias = (o < 16) ? ba[o] : bb[o - 16];
#pragma unroll
    for (int p = 0; p < 8; ++p) {
        float r = 1.f / (1.f + expf(-(acc[p] + bias)));
        int row = row0 + rg * 8 + p;
        if (o < 16) alpha[(size_t)row * 16 + o] = r;
        else        beta[(size_t)row * 16 + (o - 16)] = r;
    }
}

// ---------------------------------------------------------------------------
// K normalize over fused QKV buffer (K = cols [1024,2048))
// ---------------------------------------------------------------------------
__global__ __launch_bounds__(256) void knorm2(float* __restrict__ QKV) {
    const int w = (int)((blockIdx.x * blockDim.x + threadIdx.x) >> 5);
    const int lane = threadIdx.x & 31;
    if (w >= NROWS * H_) return;
    const int n = w >> 4, h = w & 15;
    float2* p = (float2*)(QKV + (size_t)n * 3072 + 1024 + h * 64);
    float2 v = p[lane];
    float ss = v.x * v.x + v.y * v.y;
#pragma unroll
    for (int m = 16; m; m >>= 1) ss += __shfl_xor_sync(~0u, ss, m);
    float inv = 1.f / fmaxf(sqrtf(ss), 1e-12f);
    v.x *= inv; v.y *= inv;
    p[lane] = v;
}

// ---------------------------------------------------------------------------
// Sequential scan v3: 128 blocks (one per (b,h,row-half)), 256 threads
// (2 warps/SMSP for latency hiding). Thread owns row i (of 32) and 8 cols.
// Reduction over 8 threads/row via 3 xor-shfls (lane bits 0-2, in-warp).
// Writes Y directly as fp16 into Y2 (GEMM input) — same rounding point as
// the old convert16 pass.
// ---------------------------------------------------------------------------
__global__ __launch_bounds__(256) void scan_kernel3(
    const float* __restrict__ QKV, const float* __restrict__ alpha,
    const float* __restrict__ beta, const float* __restrict__ S0,
    __half* __restrict__ Y2, float* __restrict__ Sout) {
    constexpr int CH = 16;
    __shared__ float cq[2][CH][64];
    __shared__ float ck[2][CH][64];
    __shared__ float cv[2][CH][32];
    __shared__ float ca[2][CH];
    __shared__ float cb[2][CH];

    const int tid = threadIdx.x;
    const int bh2 = blockIdx.x;          // 0..127
    const int bh = bh2 >> 1, half = bh2 & 1;
    const int b = bh >> 4, h = bh & 15;
    const int i = tid >> 3;              // row 0..31
    const int gi = half * 32 + i;        // row 0..63
    const int jg = tid & 7;              // col group
    const int j0 = jg << 3;              // 8 cols

    float4 s4[2];
    {
        const float4* sp = (const float4*)(S0 + ((size_t)bh * 64 + gi) * 64 + j0);
        s4[0] = sp[0]; s4[1] = sp[1];
    }

    const float* rowQ = QKV + (size_t)b * T_ * 3072 + (size_t)h * 64;

    auto load_chunk = [&](int t0, int buf) {
        {   // q,k: 16 steps x 64 floats = 256 float4 each; 1 per thread
            int st = tid >> 4, f = (tid & 15) << 2;
            const float* base = rowQ + (size_t)(t0 + st) * 3072;
            *(float4*)(&cq[buf][st][f]) = *(const float4*)(base + f);
            *(float4*)(&ck[buf][st][f]) = *(const float4*)(base + 1024 + f);
        }
        if (tid < 128) {   // v: 16 steps x 32 floats = 128 float4
            int st = tid >> 3, f = (tid & 7) << 2;
            const float* base = rowQ + (size_t)(t0 + st) * 3072 + 2048 + half * 32;
            *(float4*)(&cv[buf][st][f]) = *(const float4*)(base + f);
        }
        if (tid < CH)
            ca[buf][tid] = alpha[((size_t)b * T_ + t0 + tid) * H_ + h];
        else if (tid < 2 * CH)
            cb[buf][tid - CH] = beta[((size_t)b * T_ + t0 + tid - CH) * H_ + h];
    };

    const size_t ybase = (size_t)b * T_ * KP + (size_t)h * 64 + gi;  // Y2 row-major [NROWS][1024]
    const int nch = T_ / CH;
    load_chunk(0, 0);
    __syncthreads();

    for (int c = 0; c < nch; ++c) {
        const int buf = c & 1;
        if (c + 1 < nch) load_chunk((c + 1) * CH, buf ^ 1);

#pragma unroll 4
        for (int s = 0; s < CH; ++s) {
            const float a = ca[buf][s];
            const float bg = cb[buf][s];
            const float bv = bg * cv[buf][s][i];
            const float4* kp = (const float4*)(&ck[buf][s][j0]);
            const float4* qp = (const float4*)(&cq[buf][s][j0]);
            float partial = 0.f;
#pragma unroll
            for (int v = 0; v < 2; ++v) {
                float4 kk = kp[v];
                float4 qq = qp[v];
                s4[v].x = fmaf(a, s4[v].x, bv * kk.x); partial = fmaf(s4[v].x, qq.x, partial);
                s4[v].y = fmaf(a, s4[v].y, bv * kk.y); partial = fmaf(s4[v].y, qq.y, partial);
                s4[v].z = fmaf(a, s4[v].z, bv * kk.z); partial = fmaf(s4[v].z, qq.z, partial);
                s4[v].w = fmaf(a, s4[v].w, bv * kk.w); partial = fmaf(s4[v].w, qq.w, partial);
            }
            partial += __shfl_xor_sync(~0u, partial, 1);
            partial += __shfl_xor_sync(~0u, partial, 2);
            partial += __shfl_xor_sync(~0u, partial, 4);
            if (jg == 0)
                Y2[ybase + (size_t)(c * CH + s) * KP] = __float2half(partial);
        }
        __syncthreads();
    }

    float4* so = (float4*)(Sout + ((size_t)bh * 64 + gi) * 64 + j0);
    so[0] = s4[0]; so[1] = s4[1];
}

// ---------------------------------------------------------------------------
extern "C" void kernel_launch(void* const* d_in, const int* in_sizes, int n_in,
                              void* d_out, int out_size) {
    (void)in_sizes; (void)n_in;
    const float* x  = (const float*)d_in[0];
    const float* S0 = (const float*)d_in[1];
    const float* Wq = (const float*)d_in[2];
    const float* Wk = (const float*)d_in[3];
    const float* Wv = (const float*)d_in[4];
    const float* Wa = (const float*)d_in[5];
    const float* ba = (const float*)d_in[6];
    const float* Wb = (const float*)d_in[7];
    const float* bb = (const float*)d_in[8];
    const float* Wo = (const float*)d_in[9];
    float* out = (float*)d_out;

    float *QKVd, *al, *be, *Sdump, *Wab32;
    __half *A2, *Y2, *Wqkv, *Wto;
    cudaGetSymbolAddress((void**)&QKVd, g_QKV);
    cudaGetSymbolAddress((void**)&al, g_alpha);
    cudaGetSymbolAddress((void**)&be, g_beta);
    cudaGetSymbolAddress((void**)&Sdump, g_Sdump);
    cudaGetSymbolAddress((void**)&Wab32, g_Wab32);
    cudaGetSymbolAddress((void**)&A2, g_A2);
    cudaGetSymbolAddress((void**)&Y2, g_Y2);
    cudaGetSymbolAddress((void**)&Wqkv, g_Wqkv);
    cudaGetSymbolAddress((void**)&Wto, g_Wto);

    float* Sout = (out_size >= NROWS * DM_ + STATE_ELEMS) ? out + (size_t)NROWS * DM_ : Sdump;

    constexpr int GSMEM = 2 * 36864;   // 73728 per CTA (2-stage)
    cudaFuncSetAttribute(gemm_mma, cudaFuncAttributeMaxDynamicSharedMemorySize, GSMEM);

    convert16<<<NROWS, 256>>>(x, A2);
    transpose16<<<dim3(32, 32), 256>>>(Wq, Wqkv);
    transpose16<<<dim3(32, 32), 256>>>(Wk, Wqkv + (size_t)1024 * KP);
    transpose16<<<dim3(32, 32), 256>>>(Wv, Wqkv + (size_t)2048 * KP);
    transpose16<<<dim3(32, 32), 256>>>(Wo, Wto);   // <-- restored (R12 bug: missing)
    gates_prep32<<<32, 256>>>(Wa, Wb, Wab32);
    gemm_mma<<<dim3(3072 / 128, NROWS / 128), 256, GSMEM>>>(A2, Wqkv, QKVd, 3072);
    gates64<<<NROWS / 64, 256>>>(x, Wab32, ba, bb, al, be);
    knorm2<<<(NROWS * H_ * 32) / 256, 256>>>(QKVd);
    scan_kernel3<<<128, 256>>>(QKVd, al, be, S0, Y2, Sout);
    gemm_mma<<<dim3(1024 / 128, NROWS / 128), 256, GSMEM>>>(Y2, Wto, out, 1024);
}

// round 14
// speedup vs baseline: 3.4711x; 1.0227x over previous
#include <cuda_runtime.h>
#include <cuda_fp16.h>
#include <cstdint>
#include <math.h>

// Problem dims
constexpr int B_ = 4, T_ = 2048, DM_ = 1024, H_ = 16, D_ = 64;
constexpr int NROWS = B_ * T_;           // 8192
constexpr int KP = 1024;                 // plain fp16 GEMM (no split)
constexpr int STATE_ELEMS = B_ * H_ * D_ * D_;

// ---------------- scratch (device globals; allocation-free) ----------------
__device__ float g_QKV[(size_t)NROWS * 3072];   // fused Q|K|V fp32
__device__ float g_alpha[NROWS * H_];
__device__ float g_beta[NROWS * H_];
__device__ float g_Sdump[STATE_ELEMS];
__device__ float g_Wab32[32 * DM_];
__device__ __half g_A2[(size_t)NROWS * KP];
__device__ __half g_Y2[(size_t)NROWS * KP];     // scan writes fp16 directly
__device__ __half g_Wqkv[(size_t)3072 * KP];    // rows: Wq|Wk|Wv output cols
__device__ __half g_Wto[(size_t)DM_ * KP];

// ---------------------------------------------------------------------------
// fp16 mma.sync GEMM: C[8192, N] = A[8192,1024]f16 @ B[N,1024]f16^T
// R4/R10-proven mainloop: CTA 128x128, 8 warps (2M x 4N), warp tile 64x32,
// Kc=64, double-buffered cp.async, 2 CTAs/SM. smem rows padded to 72 halves.
// Epilogue: when col0 in [1024,2048) (K region of the fused QKV GEMM), each
// head (64 cols = warp pair wn&~1) is L2-normalized per row before store —
// replaces the standalone knorm2 kernel. Output-proj GEMM (grid.x=8) never
// hits this range.
// ---------------------------------------------------------------------------
__global__ __launch_bounds__(256, 2) void gemm_mma(const __half* __restrict__ A,
                                                   const __half* __restrict__ Bw,
                                                   float* __restrict__ C, int ldc) {
    extern __shared__ char sm[];
    const int tid = threadIdx.x;
    const int lane = tid & 31, wid = tid >> 5;
    const int wm = wid & 1, wn = wid >> 1;       // 2 x 4 warp grid
    const int row0 = blockIdx.y * 128;
    const int col0 = blockIdx.x * 128;

    uint32_t sb;
    asm("{ .reg .u64 t; cvta.to.shared.u64 t, %1; cvt.u32.u64 %0, t; }" : "=r"(sb) : "l"(sm));

    const uint32_t A_OFF[2] = {0u, 36864u};
    const uint32_t B_OFF[2] = {18432u, 36864u + 18432u};

    float acc[4][4][4];
#pragma unroll
    for (int i = 0; i < 4; ++i)
#pragma unroll
        for (int j = 0; j < 4; ++j)
#pragma unroll
            for (int q = 0; q < 4; ++q) acc[i][j][q] = 0.f;

    auto load_chunk = [&](int c, int buf) {
        const __half* gA = A + (size_t)row0 * KP + c * 64;
        uint32_t ab = sb + A_OFF[buf];
#pragma unroll
        for (int l = 0; l < 4; ++l) {
            int idx = tid + (l << 8);
            int r = idx >> 3, s = idx & 7;
            uint32_t so = ab + (uint32_t)(r * 144 + s * 16);
            const void* gp = gA + (size_t)r * KP + s * 8;
            asm volatile("cp.async.cg.shared.global [%0], [%1], 16;" :: "r"(so), "l"(gp));
        }
        const __half* gB = Bw + (size_t)col0 * KP + c * 64;
        uint32_t bbx = sb + B_OFF[buf];
#pragma unroll
        for (int l = 0; l < 4; ++l) {
            int idx = tid + (l << 8);
            int n = idx >> 3, s = idx & 7;
            uint32_t so = bbx + (uint32_t)(n * 144 + s * 16);
            const void* gp = gB + (size_t)n * KP + s * 8;
            asm volatile("cp.async.cg.shared.global [%0], [%1], 16;" :: "r"(so), "l"(gp));
        }
        asm volatile("cp.async.commit_group;" ::: "memory");
    };

    const uint32_t a_base = (uint32_t)((wm * 64 + (lane & 15)) * 72 + ((lane >> 4) << 3));
    const uint32_t b_base = (uint32_t)((wn * 32 + (((lane >> 4) & 1) << 3) + (lane & 7)) * 72 +
                                       (((lane >> 3) & 1) << 3));

    load_chunk(0, 0);

    constexpr int NCH = KP / 64;  // 16
    for (int c = 0; c < NCH; ++c) {
        const int buf = c & 1;
        if (c + 1 < NCH) {
            load_chunk(c + 1, buf ^ 1);
            asm volatile("cp.async.wait_group 1;" ::: "memory");
        } else {
            asm volatile("cp.async.wait_group 0;" ::: "memory");
        }
        __syncthreads();

        const uint32_t ab = sb + A_OFF[buf];
        const uint32_t bbs = sb + B_OFF[buf];
#pragma unroll
        for (int ks = 0; ks < 4; ++ks) {
            uint32_t af[4][4];
#pragma unroll
            for (int mi = 0; mi < 4; ++mi) {
                uint32_t addr = ab + (a_base + (uint32_t)(mi * 16 * 72 + ks * 16)) * 2;
                asm volatile("ldmatrix.sync.aligned.m8n8.x4.shared.b16 {%0,%1,%2,%3}, [%4];"
                             : "=r"(af[mi][0]), "=r"(af[mi][1]), "=r"(af[mi][2]), "=r"(af[mi][3])
                             : "r"(addr));
            }
            uint32_t bf[4][2];
#pragma unroll
            for (int nb = 0; nb < 2; ++nb) {
                uint32_t addr = bbs + (b_base + (uint32_t)(nb * 16 * 72 + ks * 16)) * 2;
                asm volatile("ldmatrix.sync.aligned.m8n8.x4.shared.b16 {%0,%1,%2,%3}, [%4];"
                             : "=r"(bf[2 * nb][0]), "=r"(bf[2 * nb][1]),
                               "=r"(bf[2 * nb + 1][0]), "=r"(bf[2 * nb + 1][1])
                             : "r"(addr));
            }
#pragma unroll
            for (int mi = 0; mi < 4; ++mi)
#pragma unroll
                for (int ni = 0; ni < 4; ++ni) {
                    asm volatile(
                        "mma.sync.aligned.m16n8k16.row.col.f32.f16.f16.f32 "
                        "{%0,%1,%2,%3}, {%4,%5,%6,%7}, {%8,%9}, {%0,%1,%2,%3};"
                        : "+f"(acc[mi][ni][0]), "+f"(acc[mi][ni][1]),
                          "+f"(acc[mi][ni][2]), "+f"(acc[mi][ni][3])
                        : "r"(af[mi][0]), "r"(af[mi][1]), "r"(af[mi][2]), "r"(af[mi][3]),
                          "r"(bf[ni][0]), "r"(bf[ni][1]));
                }
        }
        __syncthreads();
    }

    const int rb = row0 + wm * 64 + (lane >> 2);
    const int cb = col0 + wn * 32 + (lane & 3) * 2;

    if (col0 >= 1024 && col0 < 2048) {
        // ---- fused K L2-normalize: head = 64 cols = warp pair (wn & ~1) ----
        float* sspart = (float*)(sm + 2 * 36864);   // [4 wn][128 rows]
#pragma unroll
        for (int mi = 0; mi < 4; ++mi) {
            float s0 = 0.f, s1 = 0.f;
#pragma unroll
            for (int ni = 0; ni < 4; ++ni) {
                s0 = fmaf(acc[mi][ni][0], acc[mi][ni][0], s0);
                s0 = fmaf(acc[mi][ni][1], acc[mi][ni][1], s0);
                s1 = fmaf(acc[mi][ni][2], acc[mi][ni][2], s1);
                s1 = fmaf(acc[mi][ni][3], acc[mi][ni][3], s1);
            }
            // sum the 32 cols of this warp: 4 quad-lanes share a row
            s0 += __shfl_xor_sync(~0u, s0, 1);
            s0 += __shfl_xor_sync(~0u, s0, 2);
            s1 += __shfl_xor_sync(~0u, s1, 1);
            s1 += __shfl_xor_sync(~0u, s1, 2);
            if ((lane & 3) == 0) {
                int r0 = wm * 64 + mi * 16 + (lane >> 2);
                sspart[wn * 128 + r0] = s0;
                sspart[wn * 128 + r0 + 8] = s1;
            }
        }
        __syncthreads();
        const int base = (wn & 2) * 128;   // head's warp-pair base
#pragma unroll
        for (int mi = 0; mi < 4; ++mi) {
            int r0 = wm * 64 + mi * 16 + (lane >> 2);
            float ss0 = sspart[base + r0] + sspart[base + 128 + r0];
            float ss1 = sspart[base + r0 + 8] + sspart[base + 128 + r0 + 8];
            float inv0 = 1.f / fmaxf(sqrtf(ss0), 1e-12f);
            float inv1 = 1.f / fmaxf(sqrtf(ss1), 1e-12f);
#pragma unroll
            for (int ni = 0; ni < 4; ++ni) {
                int r = rb + mi * 16, cc = cb + ni * 8;
                *(float2*)(C + (size_t)r * ldc + cc) =
                    make_float2(acc[mi][ni][0] * inv0, acc[mi][ni][1] * inv0);
                *(float2*)(C + (size_t)(r + 8) * ldc + cc) =
                    make_float2(acc[mi][ni][2] * inv1, acc[mi][ni][3] * inv1);
            }
        }
    } else {
#pragma unroll
        for (int mi = 0; mi < 4; ++mi)
#pragma unroll
            for (int ni = 0; ni < 4; ++ni) {
                int r = rb + mi * 16, cc = cb + ni * 8;
                *(float2*)(C + (size_t)r * ldc + cc) =
                    make_float2(acc[mi][ni][0], acc[mi][ni][1]);
                *(float2*)(C + (size_t)(r + 8) * ldc + cc) =
                    make_float2(acc[mi][ni][2], acc[mi][ni][3]);
            }
    }
}

// ---------------------------------------------------------------------------
// fp32 -> fp16 flat cast
// ---------------------------------------------------------------------------
__global__ __launch_bounds__(256) void convert16(const float* __restrict__ in,
                                                 __half* __restrict__ out) {
    size_t i = (size_t)blockIdx.x * 256 + threadIdx.x;
    float4 v = ((const float4*)in)[i];
    __half2 a = __halves2half2(__float2half(v.x), __float2half(v.y));
    __half2 b = __halves2half2(__float2half(v.z), __float2half(v.w));
    __half2* o = (__half2*)out + i * 2;
    o[0] = a;
    o[1] = b;
}

// 4x W[1024][1024] fp32 -> Wt[n][1024] fp16 (transposed, K-major), one launch
__global__ __launch_bounds__(256) void transpose16x4(
    const float* __restrict__ W0, const float* __restrict__ W1,
    const float* __restrict__ W2, const float* __restrict__ W3,
    __half* __restrict__ o0, __half* __restrict__ o1,
    __half* __restrict__ o2, __half* __restrict__ o3) {
    const int z = blockIdx.z;
    const float* W = (z == 0) ? W0 : (z == 1) ? W1 : (z == 2) ? W2 : W3;
    __half* out = (z == 0) ? o0 : (z == 1) ? o1 : (z == 2) ? o2 : o3;
    __shared__ float s[32][33];
    const int tx = threadIdx.x & 31, ty = threadIdx.x >> 5;
    const int k0 = blockIdx.y << 5, n0 = blockIdx.x << 5;
#pragma unroll
    for (int r = 0; r < 32; r += 8)
        s[ty + r][tx] = W[(size_t)(k0 + ty + r) * 1024 + n0 + tx];
    __syncthreads();
#pragma unroll
    for (int r = 0; r < 32; r += 8) {
        const int n = n0 + ty + r, k = k0 + tx;
        out[(size_t)n * KP + k] = __float2half(s[tx][ty + r]);
    }
}

// Wa/Wb [1024][16] -> Wt32[32][1024] fp32
__global__ __launch_bounds__(256) void gates_prep32(const float* __restrict__ Wa,
                                                    const float* __restrict__ Wb,
                                                    float* __restrict__ out) {
    const int o = blockIdx.x;
    const float* W = (o < 16) ? Wa : Wb;
    const int h = o & 15;
    for (int k = threadIdx.x; k < 1024; k += 256)
        out[(size_t)o * 1024 + k] = W[k * 16 + h];
}

// ---------------------------------------------------------------------------
// Gates: logits = x @ Wt32^T, + bias, sigmoid. Block = 64 rows x 32 outputs.
// ---------------------------------------------------------------------------
__global__ __launch_bounds__(256) void gates64(const float* __restrict__ x,
                                               const float* __restrict__ Wt,
                                               const float* __restrict__ ba,
                                               const float* __restrict__ bb,
                                               float* __restrict__ alpha,
                                               float* __restrict__ beta) {
    __shared__ float xs[64][64];
    __shared__ float ws[32][65];
    const int tid = threadIdx.x;
    const int row0 = blockIdx.x * 64;
    const int rg = tid >> 5;
    const int o = tid & 31;

    float acc[8];
#pragma unroll
    for (int p = 0; p < 8; ++p) acc[p] = 0.f;

    for (int kc = 0; kc < 16; ++kc) {
        __syncthreads();
#pragma unroll
        for (int l = 0; l < 4; ++l) {
            int idx = tid + (l << 8);
            int r = idx >> 4, q = idx & 15;
            float4 v = *(const float4*)(x + (size_t)(row0 + r) * 1024 + kc * 64 + q * 4);
            *(float4*)(&xs[r][q * 4]) = v;
        }
#pragma unroll
        for (int l = 0; l < 2; ++l) {
            int idx = tid + (l << 8);
            int r = idx >> 4, q = idx & 15;
            float4 v = *(const float4*)(Wt + (size_t)r * 1024 + kc * 64 + q * 4);
            ws[r][q * 4 + 0] = v.x; ws[r][q * 4 + 1] = v.y;
            ws[r][q * 4 + 2] = v.z; ws[r][q * 4 + 3] = v.w;
        }
        __syncthreads();
#pragma unroll 8
        for (int k = 0; k < 64; ++k) {
            float wv = ws[o][k];
#pragma unroll
            for (int p = 0; p < 8; ++p)
                acc[p] = fmaf(xs[rg * 8 + p][k], wv, acc[p]);
        }
    }

    const float bias = (o < 16) ? ba[o] : bb[o - 16];
#pragma unroll
    for (int p = 0; p < 8; ++p) {
        float r = 1.f / (1.f + expf(-(acc[p] + bias)));
        int row = row0 + rg * 8 + p;
        if (o < 16) alpha[(size_t)row * 16 + o] = r;
        else        beta[(size_t)row * 16 + (o - 16)] = r;
    }
}

// ---------------------------------------------------------------------------
// Sequential scan v3: 128 blocks (one per (b,h,row-half)), 256 threads.
// Thread owns row i (of 32) and 8 cols; 8-lane xor-shfl reduction.
// Writes Y directly as fp16 into Y2.
// ---------------------------------------------------------------------------
__global__ __launch_bounds__(256) void scan_kernel3(
    const float* __restrict__ QKV, const float* __restrict__ alpha,
    const float* __restrict__ beta, const float* __restrict__ S0,
    __half* __restrict__ Y2, float* __restrict__ Sout) {
    constexpr int CH = 16;
    __shared__ float cq[2][CH][64];
    __shared__ float ck[2][CH][64];
    __shared__ float cv[2][CH][32];
    __shared__ float ca[2][CH];
    __shared__ float cb[2][CH];

    const int tid = threadIdx.x;
    const int bh2 = blockIdx.x;          // 0..127
    const int bh = bh2 >> 1, half = bh2 & 1;
    const int b = bh >> 4, h = bh & 15;
    const int i = tid >> 3;              // row 0..31
    const int gi = half * 32 + i;        // row 0..63
    const int jg = tid & 7;              // col group
    const int j0 = jg << 3;              // 8 cols

    float4 s4[2];
    {
        const float4* sp = (const float4*)(S0 + ((size_t)bh * 64 + gi) * 64 + j0);
        s4[0] = sp[0]; s4[1] = sp[1];
    }

    const float* rowQ = QKV + (size_t)b * T_ * 3072 + (size_t)h * 64;

    auto load_chunk = [&](int t0, int buf) {
        {
            int st = tid >> 4, f = (tid & 15) << 2;
            const float* base = rowQ + (size_t)(t0 + st) * 3072;
            *(float4*)(&cq[buf][st][f]) = *(const float4*)(base + f);
            *(float4*)(&ck[buf][st][f]) = *(const float4*)(base + 1024 + f);
        }
        if (tid < 128) {
            int st = tid >> 3, f = (tid & 7) << 2;
            const float* base = rowQ + (size_t)(t0 + st) * 3072 + 2048 + half * 32;
            *(float4*)(&cv[buf][st][f]) = *(const float4*)(base + f);
        }
        if (tid < CH)
            ca[buf][tid] = alpha[((size_t)b * T_ + t0 + tid) * H_ + h];
        else if (tid < 2 * CH)
            cb[buf][tid - CH] = beta[((size_t)b * T_ + t0 + tid - CH) * H_ + h];
    };

    const size_t ybase = (size_t)b * T_ * KP + (size_t)h * 64 + gi;
    const int nch = T_ / CH;
    load_chunk(0, 0);
    __syncthreads();

    for (int c = 0; c < nch; ++c) {
        const int buf = c & 1;
        if (c + 1 < nch) load_chunk((c + 1) * CH, buf ^ 1);

#pragma unroll 4
        for (int s = 0; s < CH; ++s) {
            const float a = ca[buf][s];
            const float bg = cb[buf][s];
            const float bv = bg * cv[buf][s][i];
            const float4* kp = (const float4*)(&ck[buf][s][j0]);
            const float4* qp = (const float4*)(&cq[buf][s][j0]);
            float partial = 0.f;
#pragma unroll
            for (int v = 0; v < 2; ++v) {
                float4 kk = kp[v];
                float4 qq = qp[v];
                s4[v].x = fmaf(a, s4[v].x, bv * kk.x); partial = fmaf(s4[v].x, qq.x, partial);
                s4[v].y = fmaf(a, s4[v].y, bv * kk.y); partial = fmaf(s4[v].y, qq.y, partial);
                s4[v].z = fmaf(a, s4[v].z, bv * kk.z); partial = fmaf(s4[v].z, qq.z, partial);
                s4[v].w = fmaf(a, s4[v].w, bv * kk.w); partial = fmaf(s4[v].w, qq.w, partial);
            }
            partial += __shfl_xor_sync(~0u, partial, 1);
            partial += __shfl_xor_sync(~0u, partial, 2);
            partial += __shfl_xor_sync(~0u, partial, 4);
            if (jg == 0)
                Y2[ybase + (size_t)(c * CH + s) * KP] = __float2half(partial);
        }
        __syncthreads();
    }

    float4* so = (float4*)(Sout + ((size_t)bh * 64 + gi) * 64 + j0);
    so[0] = s4[0]; so[1] = s4[1];
}

// ---------------------------------------------------------------------------
extern "C" void kernel_launch(void* const* d_in, const int* in_sizes, int n_in,
                              void* d_out, int out_size) {
    (void)in_sizes; (void)n_in;
    const float* x  = (const float*)d_in[0];
    const float* S0 = (const float*)d_in[1];
    const float* Wq = (const float*)d_in[2];
    const float* Wk = (const float*)d_in[3];
    const float* Wv = (const float*)d_in[4];
    const float* Wa = (const float*)d_in[5];
    const float* ba = (const float*)d_in[6];
    const float* Wb = (const float*)d_in[7];
    const float* bb = (const float*)d_in[8];
    const float* Wo = (const float*)d_in[9];
    float* out = (float*)d_out;

    float *QKVd, *al, *be, *Sdump, *Wab32;
    __half *A2, *Y2, *Wqkv, *Wto;
    cudaGetSymbolAddress((void**)&QKVd, g_QKV);
    cudaGetSymbolAddress((void**)&al, g_alpha);
    cudaGetSymbolAddress((void**)&be, g_beta);
    cudaGetSymbolAddress((void**)&Sdump, g_Sdump);
    cudaGetSymbolAddress((void**)&Wab32, g_Wab32);
    cudaGetSymbolAddress((void**)&A2, g_A2);
    cudaGetSymbolAddress((void**)&Y2, g_Y2);
    cudaGetSymbolAddress((void**)&Wqkv, g_Wqkv);
    cudaGetSymbolAddress((void**)&Wto, g_Wto);

    float* Sout = (out_size >= NROWS * DM_ + STATE_ELEMS) ? out + (size_t)NROWS * DM_ : Sdump;

    constexpr int GSMEM = 2 * 36864 + 4 * 128 * 4;   // stages + knorm partials = 75776
    cudaFuncSetAttribute(gemm_mma, cudaFuncAttributeMaxDynamicSharedMemorySize, GSMEM);

    convert16<<<NROWS, 256>>>(x, A2);
    transpose16x4<<<dim3(32, 32, 4), 256>>>(Wq, Wk, Wv, Wo,
                                            Wqkv,
                                            Wqkv + (size_t)1024 * KP,
                                            Wqkv + (size_t)2048 * KP,
                                            Wto);
    gates_prep32<<<32, 256>>>(Wa, Wb, Wab32);
    gemm_mma<<<dim3(3072 / 128, NROWS / 128), 256, GSMEM>>>(A2, Wqkv, QKVd, 3072);  // + fused knorm
    gates64<<<NROWS / 64, 256>>>(x, Wab32, ba, bb, al, be);
    scan_kernel3<<<128, 256>>>(QKVd, al, be, S0, Y2, Sout);
    gemm_mma<<<dim3(1024 / 128, NROWS / 128), 256, GSMEM>>>(Y2, Wto, out, 1024);
}